// round 15
// baseline (speedup 1.0000x reference)
#include <cuda_runtime.h>
#include <cuda_bf16.h>
#include <math.h>
#include <stdint.h>

// ---------------- problem constants ----------------
constexpr int NN   = 65536;
constexpr int NE   = 524288;
constexpr int ET   = NE + NN;
constexpr int GS   = 512;
constexpr int NG   = NN / GS;
constexpr int D1   = 256;
constexpr int D3   = 128;
constexpr int PERS = 296;   // 148 SMs x 2 CTAs

// ---------------- fp32 scratch ----------------
constexpr size_t OFF_H    = 0;
constexpr size_t OFF_H3   = OFF_H  + (size_t)NN*D1;
constexpr size_t OFF_R    = OFF_H3 + (size_t)NN*D3;
constexpr size_t OFF_ES   = OFF_R  + (size_t)NN*D3;
constexpr size_t OFF_ED   = OFF_ES + (size_t)NN*4;
constexpr size_t SCRATCH  = OFF_ED + (size_t)NN*4;

__device__ __align__(256) float g_scratch[SCRATCH];

// ---------------- bf16 scratch ----------------
constexpr size_t B_XH  = 0;
constexpr size_t B_XL  = B_XH  + (size_t)NN*64;
constexpr size_t B_TH  = B_XL  + (size_t)NN*64;
constexpr size_t B_TL  = B_TH  + (size_t)NN*256;
constexpr size_t B_HRH = B_TL  + (size_t)NN*256;
constexpr size_t B_HRL = B_HRH + (size_t)NN*128;
constexpr size_t B_AOH = B_HRL + (size_t)NN*128;
constexpr size_t B_AOL = B_AOH + (size_t)NN*128;
constexpr size_t B_QH  = B_AOL + (size_t)NN*128;
constexpr size_t B_QL  = B_QH  + (size_t)NN*128;
constexpr size_t B_KH  = B_QL  + (size_t)NN*128;
constexpr size_t B_KL  = B_KH  + (size_t)NN*128;
constexpr size_t B_VH  = B_KL  + (size_t)NN*128;
constexpr size_t B_VL  = B_VH  + (size_t)NN*128;
constexpr size_t B_W1RH = B_VL  + (size_t)NN*128;   // concat [W1;Wr]^T: 384x64
constexpr size_t B_W1RL = B_W1RH + 384*64;
constexpr size_t B_W2H = B_W1RL + 384*64;
constexpr size_t B_W2L = B_W2H + 256*256;
constexpr size_t B_W3H = B_W2L + 256*256;
constexpr size_t B_W3L = B_W3H + 128*256;
constexpr size_t B_WQKVH = B_W3L + 128*256;
constexpr size_t B_WQKVL = B_WQKVH + 384*128;
constexpr size_t B_WOH = B_WQKVL + 384*128;
constexpr size_t B_WOL = B_WOH + 128*128;
constexpr size_t BF_TOTAL = B_WOL + 128*128;

__device__ __align__(256) __nv_bfloat16 g_bf[BF_TOTAL];

__device__ int g_rowptr[NN + 1];
__device__ int g_cnt[NN];
__device__ int g_cursor[NN];
__device__ int g_col[ET];
__device__ int g_blocksum[256];

// ================= helpers =================
__device__ __forceinline__ uint32_t smem_u32(const void* p) {
    uint32_t a;
    asm("{ .reg .u64 t; cvta.to.shared.u64 t, %1; cvt.u32.u64 %0, t; }" : "=r"(a) : "l"(p));
    return a;
}
#define LDMX4(r, a) \
    asm volatile("ldmatrix.sync.aligned.m8n8.x4.shared.b16 {%0,%1,%2,%3}, [%4];" \
        : "=r"((r)[0]), "=r"((r)[1]), "=r"((r)[2]), "=r"((r)[3]) : "r"(a))
#define LDMX4T(r, a) \
    asm volatile("ldmatrix.sync.aligned.m8n8.x4.trans.shared.b16 {%0,%1,%2,%3}, [%4];" \
        : "=r"((r)[0]), "=r"((r)[1]), "=r"((r)[2]), "=r"((r)[3]) : "r"(a))
#define MMA16816(d, a, b) \
    asm volatile("mma.sync.aligned.m16n8k16.row.col.f32.bf16.bf16.f32 " \
        "{%0,%1,%2,%3}, {%4,%5,%6,%7}, {%8,%9}, {%0,%1,%2,%3};" \
        : "+f"((d)[0]), "+f"((d)[1]), "+f"((d)[2]), "+f"((d)[3]) \
        : "r"((a)[0]), "r"((a)[1]), "r"((a)[2]), "r"((a)[3]), \
          "r"((b)[0]), "r"((b)[1]))
#define CP16(dst, src) \
    asm volatile("cp.async.cg.shared.global [%0], [%1], 16;" :: "r"(dst), "l"(src))
#define CP_COMMIT() asm volatile("cp.async.commit_group;" ::: "memory")
#define CP_WAIT1()  asm volatile("cp.async.wait_group 1;" ::: "memory")
#define CP_WAIT0()  asm volatile("cp.async.wait_group 0;" ::: "memory")

__device__ __forceinline__ void split2(float v0, float v1, uint32_t& hh, uint32_t& ll) {
    __nv_bfloat16 h0 = __float2bfloat16(v0), h1 = __float2bfloat16(v1);
    __nv_bfloat16 l0 = __float2bfloat16(v0 - __bfloat162float(h0));
    __nv_bfloat16 l1 = __float2bfloat16(v1 - __bfloat162float(h1));
    __nv_bfloat162 H; H.x = h0; H.y = h1;
    __nv_bfloat162 L; L.x = l0; L.y = l1;
    hh = *(uint32_t*)&H; ll = *(uint32_t*)&L;
}

// ================= CSR build =================
__global__ void k_count(const int* __restrict__ ei) {
    int stride = gridDim.x * blockDim.x;
    for (int idx = blockIdx.x * blockDim.x + threadIdx.x; idx < NE; idx += stride)
        atomicAdd(&g_cnt[ei[NE + idx]], 1);
}
__global__ void k_scan1() {
    __shared__ int ws[8];
    int b = blockIdx.x, tid = threadIdx.x, lane = tid & 31, wid = tid >> 5;
    int v = g_cnt[b * 256 + tid] + 1;
    int x = v;
    #pragma unroll
    for (int o = 1; o < 32; o <<= 1) {
        int t = __shfl_up_sync(0xffffffffu, x, o);
        if (lane >= o) x += t;
    }
    if (lane == 31) ws[wid] = x;
    __syncthreads();
    if (tid == 0) {
        int run = 0;
        #pragma unroll
        for (int k = 0; k < 8; k++) { int t = ws[k]; ws[k] = run; run += t; }
        g_blocksum[b] = run;
    }
    __syncthreads();
    g_rowptr[b * 256 + tid] = x - v + ws[wid];
}
__global__ void k_scan3() {
    __shared__ int red[8];
    __shared__ int s_off;
    int b = blockIdx.x, tid = threadIdx.x, lane = tid & 31, wid = tid >> 5;
    int v = (tid < b) ? g_blocksum[tid] : 0;
    #pragma unroll
    for (int o = 16; o; o >>= 1) v += __shfl_xor_sync(0xffffffffu, v, o);
    if (lane == 0) red[wid] = v;
    __syncthreads();
    if (tid == 0) {
        int t = 0;
        #pragma unroll
        for (int k = 0; k < 8; k++) t += red[k];
        s_off = t;
    }
    __syncthreads();
    int idx = b * 256 + tid;
    int val = g_rowptr[idx] + s_off;
    g_rowptr[idx] = val;
    g_cursor[idx] = val;
    if (idx == 0) g_rowptr[NN] = ET;
}
__global__ void k_fill(const int* __restrict__ ei) {
    int stride = gridDim.x * blockDim.x;
    for (int idx = blockIdx.x * blockDim.x + threadIdx.x; idx < ET; idx += stride) {
        int s, d;
        if (idx < NE) { s = ei[idx]; d = ei[NE + idx]; }
        else          { s = d = idx - NE; }
        int pos = atomicAdd(&g_cursor[d], 1);
        g_col[pos] = s;
    }
}

// ============ conversions: weights + x + g_cnt zeroing in ONE launch =========
constexpr int WSEG0 = 384 * 64;                 // W1R
constexpr int WSEG1 = WSEG0 + 256 * 256;        // W2
constexpr int WSEG2 = WSEG1 + 128 * 256;        // W3
constexpr int WSEG3 = WSEG2 + 384 * 128;        // WQKV
constexpr int WSEG4 = WSEG3 + 128 * 128;        // WO
constexpr int XGROUPS = NN * 64 / 4;            // x as float4 groups
constexpr int ZSEG = NN / 4;                    // g_cnt zero as int4 groups
constexpr int CVT_TOTAL = WSEG4 + XGROUPS + ZSEG;
__global__ void k_cvt_all(const float* __restrict__ W1, const float* __restrict__ Wr,
                          const float* __restrict__ W2, const float* __restrict__ W3,
                          const float* __restrict__ Wq, const float* __restrict__ Wk,
                          const float* __restrict__ Wv, const float* __restrict__ Wo,
                          const float* __restrict__ x) {
    int idx = blockIdx.x * blockDim.x + threadIdx.x;
    if (idx >= CVT_TOTAL) return;
    if (idx >= WSEG4 + XGROUPS) {
        int i = idx - WSEG4 - XGROUPS;
        ((int4*)g_cnt)[i] = make_int4(0, 0, 0, 0);
        return;
    }
    if (idx >= WSEG4) {
        int i = idx - WSEG4;
        float4 v = ((const float4*)x)[i];
        uint32_t h01, l01, h23, l23;
        split2(v.x, v.y, h01, l01);
        split2(v.z, v.w, h23, l23);
        ((uint32_t*)(g_bf + B_XH))[2 * i] = h01;
        ((uint32_t*)(g_bf + B_XH))[2 * i + 1] = h23;
        ((uint32_t*)(g_bf + B_XL))[2 * i] = l01;
        ((uint32_t*)(g_bf + B_XL))[2 * i + 1] = l23;
        return;
    }
    float v;
    size_t hoff, loff;
    if (idx < WSEG0) {
        int li = idx, n = li / 64, k = li % 64;
        v = (n < 256) ? W1[(size_t)k * 256 + n] : Wr[(size_t)k * 128 + (n - 256)];
        hoff = B_W1RH + li; loff = B_W1RL + li;
    } else if (idx < WSEG1) {
        int li = idx - WSEG0, n = li / 256, k = li % 256;
        v = W2[(size_t)k * 256 + n];
        hoff = B_W2H + li; loff = B_W2L + li;
    } else if (idx < WSEG2) {
        int li = idx - WSEG1, n = li / 256, k = li % 256;
        v = W3[(size_t)k * 128 + n];
        hoff = B_W3H + li; loff = B_W3L + li;
    } else if (idx < WSEG3) {
        int li = idx - WSEG2, n = li / 128, k = li % 128;
        const float* W = (n < 128) ? Wq : ((n < 256) ? Wk : Wv);
        v = W[(size_t)k * 128 + (n & 127)];
        hoff = B_WQKVH + li; loff = B_WQKVL + li;
    } else {
        int li = idx - WSEG3, n = li / 128, k = li % 128;
        v = Wo[(size_t)k * 128 + n];
        hoff = B_WOH + li; loff = B_WOL + li;
    }
    __nv_bfloat16 h = __float2bfloat16(v);
    g_bf[hoff] = h;
    g_bf[loff] = __float2bfloat16(v - __bfloat162float(h));
}

// ================= mma.sync bf16-split GEMM, persistent tiles ================
constexpr int LDS_ = 40;
constexpr int G_OAL = 128 * LDS_;
constexpr int G_OBH = 2 * 128 * LDS_;
constexpr int G_OBL = 3 * 128 * LDS_;
constexpr int G_STAGE = 4 * 128 * LDS_;
constexpr int GEMM_SMEM = 2 * G_STAGE * 2;

__global__ __launch_bounds__(256, 2) void mma_gemm(
    const __nv_bfloat16* __restrict__ Ah, const __nv_bfloat16* __restrict__ Al,
    const __nv_bfloat16* __restrict__ Bh, const __nv_bfloat16* __restrict__ Bl,
    const float* __restrict__ bias, float* __restrict__ C,
    __nv_bfloat16* __restrict__ Chi, __nv_bfloat16* __restrict__ Clo,
    float* __restrict__ C2, const float* __restrict__ bias2,
    const float* __restrict__ asv, const float* __restrict__ adv,
    float* __restrict__ esv, float* __restrict__ edv_out,
    int score_mode, int M, int N, int K)
{
    extern __shared__ __nv_bfloat16 smem[];
    int tid = threadIdx.x, lane = tid & 31, warp = tid >> 5;
    int wm = warp & 3, wn = warp >> 2;
    int nbn = N >> 7;
    int ntiles = (M >> 7) * nbn;
    int row_c = tid >> 2, seg_c = (tid & 3) * 8;
    int nch = K >> 5;

    for (int tile = blockIdx.x; tile < ntiles; tile += gridDim.x) {
        int bm = tile / nbn, bn = tile - bm * nbn;
        const __nv_bfloat16* gAh = Ah + (size_t)bm * 128 * K;
        const __nv_bfloat16* gAl = Al + (size_t)bm * 128 * K;
        const __nv_bfloat16* gBh = Bh + (size_t)bn * 128 * K;
        const __nv_bfloat16* gBl = Bl + (size_t)bn * 128 * K;

        auto issue = [&](int ich, int st) {
            int k0 = ich << 5;
            __nv_bfloat16* s = smem + st * G_STAGE;
            #pragma unroll
            for (int r = 0; r < 2; r++) {
                int row = row_c + r * 64;
                size_t go = (size_t)row * K + k0 + seg_c;
                int so = row * LDS_ + seg_c;
                CP16(smem_u32(s + so), gAh + go);
                CP16(smem_u32(s + G_OAL + so), gAl + go);
                CP16(smem_u32(s + G_OBH + so), gBh + go);
                CP16(smem_u32(s + G_OBL + so), gBl + go);
            }
            CP_COMMIT();
        };

        float d[2][8][4];
        #pragma unroll
        for (int mi = 0; mi < 2; mi++)
            #pragma unroll
            for (int ni = 0; ni < 8; ni++)
                #pragma unroll
                for (int j = 0; j < 4; j++) d[mi][ni][j] = 0.f;

        issue(0, 0);
        if (nch > 1) issue(1, 1);

        for (int ich = 0; ich < nch; ich++) {
            if (ich + 1 < nch) CP_WAIT1(); else CP_WAIT0();
            __syncthreads();
            const __nv_bfloat16* s = smem + (ich & 1) * G_STAGE;
            #pragma unroll
            for (int ks = 0; ks < 2; ks++) {
                uint32_t ah[2][4], al[2][4];
                #pragma unroll
                for (int mi = 0; mi < 2; mi++) {
                    int row = wm * 32 + mi * 16 + (lane & 15);
                    int col = ks * 16 + (lane >> 4) * 8;
                    LDMX4(ah[mi], smem_u32(s + row * LDS_ + col));
                    LDMX4(al[mi], smem_u32(s + G_OAL + row * LDS_ + col));
                }
                int brow = wn * 64 + ((lane >> 4) & 1) * 8 + (lane & 7);
                int bcol = ks * 16 + ((lane >> 3) & 1) * 8;
                #pragma unroll
                for (int p = 0; p < 4; p++) {
                    uint32_t bh4[4], bl4[4];
                    int off = (brow + p * 16) * LDS_ + bcol;
                    LDMX4(bh4, smem_u32(s + G_OBH + off));
                    LDMX4(bl4, smem_u32(s + G_OBL + off));
                    #pragma unroll
                    for (int mi = 0; mi < 2; mi++) {
                        MMA16816(d[mi][2 * p],     ah[mi], bh4);
                        MMA16816(d[mi][2 * p],     al[mi], bh4);
                        MMA16816(d[mi][2 * p],     ah[mi], bl4);
                        MMA16816(d[mi][2 * p + 1], ah[mi], bh4 + 2);
                        MMA16816(d[mi][2 * p + 1], al[mi], bh4 + 2);
                        MMA16816(d[mi][2 * p + 1], ah[mi], bl4 + 2);
                    }
                }
            }
            __syncthreads();
            if (ich + 2 < nch) issue(ich + 2, ich & 1);
        }

        // epilogue
        if (score_mode == 3 && bn == 2) {
            #pragma unroll
            for (int mi = 0; mi < 2; mi++) {
                int row = bm * 128 + wm * 32 + mi * 16 + (lane >> 2);
                #pragma unroll
                for (int ni = 0; ni < 8; ni++) {
                    int col = wn * 64 + ni * 8 + (lane & 3) * 2;
                    float b0 = bias2[col], b1 = bias2[col + 1];
                    *(float2*)(C2 + (size_t)row * 128 + col) =
                        make_float2(d[mi][ni][0] + b0, d[mi][ni][1] + b1);
                    *(float2*)(C2 + (size_t)(row + 8) * 128 + col) =
                        make_float2(d[mi][ni][2] + b0, d[mi][ni][3] + b1);
                }
            }
        } else {
            int outN = (score_mode == 3) ? 256 : N;
            #pragma unroll
            for (int mi = 0; mi < 2; mi++) {
                int row = bm * 128 + wm * 32 + mi * 16 + (lane >> 2);
                #pragma unroll
                for (int ni = 0; ni < 8; ni++) {
                    int col = bn * 128 + wn * 64 + ni * 8 + (lane & 3) * 2;
                    if (C) {
                        float b0 = bias ? bias[col] : 0.f;
                        float b1 = bias ? bias[col + 1] : 0.f;
                        *(float2*)(C + (size_t)row * outN + col) =
                            make_float2(d[mi][ni][0] + b0, d[mi][ni][1] + b1);
                        *(float2*)(C + (size_t)(row + 8) * outN + col) =
                            make_float2(d[mi][ni][2] + b0, d[mi][ni][3] + b1);
                    } else {
                        uint32_t hh, ll;
                        split2(d[mi][ni][0], d[mi][ni][1], hh, ll);
                        *(uint32_t*)(Chi + (size_t)row * outN + col) = hh;
                        *(uint32_t*)(Clo + (size_t)row * outN + col) = ll;
                        split2(d[mi][ni][2], d[mi][ni][3], hh, ll);
                        *(uint32_t*)(Chi + (size_t)(row + 8) * outN + col) = hh;
                        *(uint32_t*)(Clo + (size_t)(row + 8) * outN + col) = ll;
                    }
                }
            }
        }
        if (score_mode == 1 || (score_mode == 3 && bn < 2)) {
            int hd = bn * 2 + wn;
            float sv[4] = {0.f, 0.f, 0.f, 0.f}, dv[4] = {0.f, 0.f, 0.f, 0.f};
            #pragma unroll
            for (int mi = 0; mi < 2; mi++)
                #pragma unroll
                for (int ni = 0; ni < 8; ni++)
                    #pragma unroll
                    for (int j = 0; j < 2; j++) {
                        int cl = ni * 8 + (lane & 3) * 2 + j;
                        float a = asv[hd * 64 + cl], b = adv[hd * 64 + cl];
                        sv[mi * 2]     += d[mi][ni][j]     * a;
                        dv[mi * 2]     += d[mi][ni][j]     * b;
                        sv[mi * 2 + 1] += d[mi][ni][2 + j] * a;
                        dv[mi * 2 + 1] += d[mi][ni][2 + j] * b;
                    }
            #pragma unroll
            for (int r = 0; r < 4; r++) {
                sv[r] += __shfl_xor_sync(0xffffffffu, sv[r], 1);
                sv[r] += __shfl_xor_sync(0xffffffffu, sv[r], 2);
                dv[r] += __shfl_xor_sync(0xffffffffu, dv[r], 1);
                dv[r] += __shfl_xor_sync(0xffffffffu, dv[r], 2);
            }
            if ((lane & 3) == 0) {
                #pragma unroll
                for (int r = 0; r < 4; r++) {
                    int row = bm * 128 + wm * 32 + (r >> 1) * 16 + (lane >> 2) + (r & 1) * 8;
                    esv[(size_t)row * 4 + hd]     = sv[r];
                    edv_out[(size_t)row * 4 + hd] = dv[r];
                }
            }
        } else if (score_mode == 2) {
            float* reds = (float*)smem;
            float* redd = reds + 256;
            float sv[4] = {0.f, 0.f, 0.f, 0.f}, dv[4] = {0.f, 0.f, 0.f, 0.f};
            #pragma unroll
            for (int mi = 0; mi < 2; mi++)
                #pragma unroll
                for (int ni = 0; ni < 8; ni++)
                    #pragma unroll
                    for (int j = 0; j < 2; j++) {
                        int cl = wn * 64 + ni * 8 + (lane & 3) * 2 + j;
                        float a = asv[cl], b = adv[cl];
                        sv[mi * 2]     += d[mi][ni][j]     * a;
                        dv[mi * 2]     += d[mi][ni][j]     * b;
                        sv[mi * 2 + 1] += d[mi][ni][2 + j] * a;
                        dv[mi * 2 + 1] += d[mi][ni][2 + j] * b;
                    }
            #pragma unroll
            for (int r = 0; r < 4; r++) {
                sv[r] += __shfl_xor_sync(0xffffffffu, sv[r], 1);
                sv[r] += __shfl_xor_sync(0xffffffffu, sv[r], 2);
                dv[r] += __shfl_xor_sync(0xffffffffu, dv[r], 1);
                dv[r] += __shfl_xor_sync(0xffffffffu, dv[r], 2);
            }
            __syncthreads();
            if ((lane & 3) == 0) {
                #pragma unroll
                for (int r = 0; r < 4; r++) {
                    int row = wm * 32 + (r >> 1) * 16 + (lane >> 2) + (r & 1) * 8;
                    reds[row * 2 + wn] = sv[r];
                    redd[row * 2 + wn] = dv[r];
                }
            }
            __syncthreads();
            if (tid < 128) {
                esv[(size_t)(bm * 128 + tid)]     = reds[tid * 2] + reds[tid * 2 + 1];
                edv_out[(size_t)(bm * 128 + tid)] = redd[tid * 2] + redd[tid * 2 + 1];
            }
            __syncthreads();
        }
    }
}

// ================= QKV fused GEMM (persistent) =================
__global__ __launch_bounds__(256, 2) void mma_gemm_qkv(
    const __nv_bfloat16* __restrict__ Ah, const __nv_bfloat16* __restrict__ Al,
    const __nv_bfloat16* __restrict__ Bh, const __nv_bfloat16* __restrict__ Bl,
    __nv_bfloat16* __restrict__ QH, __nv_bfloat16* __restrict__ QL,
    __nv_bfloat16* __restrict__ KH, __nv_bfloat16* __restrict__ KL,
    __nv_bfloat16* __restrict__ VH, __nv_bfloat16* __restrict__ VL)
{
    constexpr int K = 128;
    constexpr int nch = K >> 5;
    extern __shared__ __nv_bfloat16 smem[];
    int tid = threadIdx.x, lane = tid & 31, warp = tid >> 5;
    int wm = warp & 3, wn = warp >> 2;
    int row_c = tid >> 2, seg_c = (tid & 3) * 8;
    constexpr int ntiles = 3 * 512;

    for (int tile = blockIdx.x; tile < ntiles; tile += gridDim.x) {
        int bm = tile / 3, bn = tile - bm * 3;
        const __nv_bfloat16* gAh = Ah + (size_t)bm * 128 * K;
        const __nv_bfloat16* gAl = Al + (size_t)bm * 128 * K;
        const __nv_bfloat16* gBh = Bh + (size_t)bn * 128 * K;
        const __nv_bfloat16* gBl = Bl + (size_t)bn * 128 * K;

        auto issue = [&](int ich, int st) {
            int k0 = ich << 5;
            __nv_bfloat16* s = smem + st * G_STAGE;
            #pragma unroll
            for (int r = 0; r < 2; r++) {
                int row = row_c + r * 64;
                size_t go = (size_t)row * K + k0 + seg_c;
                int so = row * LDS_ + seg_c;
                CP16(smem_u32(s + so), gAh + go);
                CP16(smem_u32(s + G_OAL + so), gAl + go);
                CP16(smem_u32(s + G_OBH + so), gBh + go);
                CP16(smem_u32(s + G_OBL + so), gBl + go);
            }
            CP_COMMIT();
        };

        float d[2][8][4];
        #pragma unroll
        for (int mi = 0; mi < 2; mi++)
            #pragma unroll
            for (int ni = 0; ni < 8; ni++)
                #pragma unroll
                for (int j = 0; j < 4; j++) d[mi][ni][j] = 0.f;

        issue(0, 0);
        issue(1, 1);
        for (int ich = 0; ich < nch; ich++) {
            if (ich + 1 < nch) CP_WAIT1(); else CP_WAIT0();
            __syncthreads();
            const __nv_bfloat16* s = smem + (ich & 1) * G_STAGE;
            #pragma unroll
            for (int ks = 0; ks < 2; ks++) {
                uint32_t ah[2][4], al[2][4];
                #pragma unroll
                for (int mi = 0; mi < 2; mi++) {
                    int row = wm * 32 + mi * 16 + (lane & 15);
                    int col = ks * 16 + (lane >> 4) * 8;
                    LDMX4(ah[mi], smem_u32(s + row * LDS_ + col));
                    LDMX4(al[mi], smem_u32(s + G_OAL + row * LDS_ + col));
                }
                int brow = wn * 64 + ((lane >> 4) & 1) * 8 + (lane & 7);
                int bcol = ks * 16 + ((lane >> 3) & 1) * 8;
                #pragma unroll
                for (int p = 0; p < 4; p++) {
                    uint32_t bh4[4], bl4[4];
                    int off = (brow + p * 16) * LDS_ + bcol;
                    LDMX4(bh4, smem_u32(s + G_OBH + off));
                    LDMX4(bl4, smem_u32(s + G_OBL + off));
                    #pragma unroll
                    for (int mi = 0; mi < 2; mi++) {
                        MMA16816(d[mi][2 * p],     ah[mi], bh4);
                        MMA16816(d[mi][2 * p],     al[mi], bh4);
                        MMA16816(d[mi][2 * p],     ah[mi], bl4);
                        MMA16816(d[mi][2 * p + 1], ah[mi], bh4 + 2);
                        MMA16816(d[mi][2 * p + 1], al[mi], bh4 + 2);
                        MMA16816(d[mi][2 * p + 1], ah[mi], bl4 + 2);
                    }
                }
            }
            __syncthreads();
            if (ich + 2 < nch) issue(ich + 2, ich & 1);
        }
        __nv_bfloat16 *Oh, *Ol;
        if (bn == 0)      { Oh = QH; Ol = QL; }
        else if (bn == 1) { Oh = KH; Ol = KL; }
        else              { Oh = VH; Ol = VL; }
        #pragma unroll
        for (int mi = 0; mi < 2; mi++) {
            int row = bm * 128 + wm * 32 + mi * 16 + (lane >> 2);
            #pragma unroll
            for (int ni = 0; ni < 8; ni++) {
                int col = wn * 64 + ni * 8 + (lane & 3) * 2;
                uint32_t hh, ll;
                split2(d[mi][ni][0], d[mi][ni][1], hh, ll);
                *(uint32_t*)(Oh + (size_t)row * 128 + col) = hh;
                *(uint32_t*)(Ol + (size_t)row * 128 + col) = ll;
                split2(d[mi][ni][2], d[mi][ni][3], hh, ll);
                *(uint32_t*)(Oh + (size_t)(row + 8) * 128 + col) = hh;
                *(uint32_t*)(Ol + (size_t)(row + 8) * 128 + col) = ll;
            }
        }
    }
}

// ================= GAT aggregation — single pass, float4 vectorized ==========
template <int D, int H>
__global__ __launch_bounds__(256) void k_gat_agg(
    const float* __restrict__ hfeat, const float* __restrict__ es,
    const float* __restrict__ ed, const float* __restrict__ bias,
    const float* __restrict__ gamma, const float* __restrict__ beta,
    const float* __restrict__ resid,
    __nv_bfloat16* __restrict__ outH, __nv_bfloat16* __restrict__ outL)
{
    constexpr int C = D / H;
    constexpr int NV = D / 128;
    int warp = (blockIdx.x * blockDim.x + threadIdx.x) >> 5;
    int lane = threadIdx.x & 31;
    if (warp >= NN) return;
    int i = warp;
    int beg = g_rowptr[i], end = g_rowptr[i + 1];

    float edv[H], z[H];
    #pragma unroll
    for (int h = 0; h < H; h++) {
        edv[h] = ed[(size_t)i * H + h];
        z[h] = 0.f;
    }
    float4 acc[NV];
    #pragma unroll
    for (int j = 0; j < NV; j++) acc[j] = make_float4(0.f, 0.f, 0.f, 0.f);

    for (int e = beg; e < end; e++) {
        int s = g_col[e];
        float al[H];
        if (H == 4) {
            float4 ev = ((const float4*)es)[s];
            float vv[4] = {ev.x, ev.y, ev.z, ev.w};
            #pragma unroll
            for (int h = 0; h < 4; h++) {
                float v = vv[h] + edv[h];
                v = v > 0.f ? v : 0.2f * v;
                al[h] = __expf(v);
                z[h] += al[h];
            }
        } else {
            float v = es[s] + edv[0];
            v = v > 0.f ? v : 0.2f * v;
            al[0] = __expf(v);
            z[0] += al[0];
        }
        const float4* hs = (const float4*)(hfeat + (size_t)s * D);
        #pragma unroll
        for (int j = 0; j < NV; j++) {
            float4 hv = hs[lane + 32 * j];
            float a = (H == 1) ? al[0] : al[((lane + 32 * j) * 4) / C];
            acc[j].x += a * hv.x; acc[j].y += a * hv.y;
            acc[j].z += a * hv.z; acc[j].w += a * hv.w;
        }
    }
    #pragma unroll
    for (int h = 0; h < H; h++) z[h] = 1.f / (z[h] + 1e-16f);

    float4 x[NV];
    #pragma unroll
    for (int j = 0; j < NV; j++) {
        int g4 = lane + 32 * j;
        float zz = (H == 1) ? z[0] : z[(g4 * 4) / C];
        float4 b4 = ((const float4*)bias)[g4];
        x[j].x = acc[j].x * zz + b4.x;
        x[j].y = acc[j].y * zz + b4.y;
        x[j].z = acc[j].z * zz + b4.z;
        x[j].w = acc[j].w * zz + b4.w;
        if (resid) {
            float4 r4 = ((const float4*)(resid + (size_t)i * D))[g4];
            x[j].x += r4.x; x[j].y += r4.y; x[j].z += r4.z; x[j].w += r4.w;
        }
    }
    if (gamma) {
        #pragma unroll
        for (int j = 0; j < NV; j++) {
            x[j].x = x[j].x > 0.f ? x[j].x : (__expf(x[j].x) - 1.f);
            x[j].y = x[j].y > 0.f ? x[j].y : (__expf(x[j].y) - 1.f);
            x[j].z = x[j].z > 0.f ? x[j].z : (__expf(x[j].z) - 1.f);
            x[j].w = x[j].w > 0.f ? x[j].w : (__expf(x[j].w) - 1.f);
        }
        float s = 0.f;
        #pragma unroll
        for (int j = 0; j < NV; j++) s += x[j].x + x[j].y + x[j].z + x[j].w;
        #pragma unroll
        for (int o = 16; o; o >>= 1) s += __shfl_xor_sync(0xffffffffu, s, o);
        float mu = s / (float)D;
        float vs = 0.f;
        #pragma unroll
        for (int j = 0; j < NV; j++) {
            float a = x[j].x - mu, b = x[j].y - mu, c = x[j].z - mu, dd = x[j].w - mu;
            vs += a * a + b * b + c * c + dd * dd;
        }
        #pragma unroll
        for (int o = 16; o; o >>= 1) vs += __shfl_xor_sync(0xffffffffu, vs, o);
        float inv = rsqrtf(vs / (float)D + 1e-5f);
        #pragma unroll
        for (int j = 0; j < NV; j++) {
            int g4 = lane + 32 * j;
            float4 g = ((const float4*)gamma)[g4];
            float4 be = ((const float4*)beta)[g4];
            x[j].x = (x[j].x - mu) * inv * g.x + be.x;
            x[j].y = (x[j].y - mu) * inv * g.y + be.y;
            x[j].z = (x[j].z - mu) * inv * g.z + be.z;
            x[j].w = (x[j].w - mu) * inv * g.w + be.w;
        }
    }
    #pragma unroll
    for (int j = 0; j < NV; j++) {
        int g4 = lane + 32 * j;
        uint32_t h01, l01, h23, l23;
        split2(x[j].x, x[j].y, h01, l01);
        split2(x[j].z, x[j].w, h23, l23);
        *(uint2*)(outH + (size_t)i * D + g4 * 4) = make_uint2(h01, h23);
        *(uint2*)(outL + (size_t)i * D + g4 * 4) = make_uint2(l01, l23);
    }
}

// ========== fused flash attention, cp.async K/V pipeline, PERSISTENT =========
constexpr int FL_QH = 0;
constexpr int FL_QL = 128 * LDS_;
constexpr int FL_ST0 = 2 * 128 * LDS_;
constexpr int FL_KH = 0;
constexpr int FL_KL = 128 * LDS_;
constexpr int FL_VH = 2 * 128 * LDS_;
constexpr int FL_VL = 3 * 128 * LDS_;
constexpr int FL_STAGE = 4 * 128 * LDS_;
constexpr int FLASH_SMEM = (FL_ST0 + 2 * FL_STAGE) * 2;   // 102400 bytes

__global__ __launch_bounds__(256, 2) void k_flash(
    const __nv_bfloat16* __restrict__ QH, const __nv_bfloat16* __restrict__ QL,
    const __nv_bfloat16* __restrict__ KH, const __nv_bfloat16* __restrict__ KL,
    const __nv_bfloat16* __restrict__ VH, const __nv_bfloat16* __restrict__ VL,
    __nv_bfloat16* __restrict__ OHo, __nv_bfloat16* __restrict__ OLo)
{
    extern __shared__ __nv_bfloat16 sm[];
    int tid = threadIdx.x, lane = tid & 31, warp = tid >> 5;
    int row_c = tid >> 2, seg_c = (tid & 3) * 8;
    constexpr int NTILES = NG * 4 * 4;   // (gh, qt)

    for (int t = blockIdx.x; t < NTILES; t += gridDim.x) {
        int gh = t >> 2, qt = t & 3;
        int g = gh >> 2, h = gh & 3;

        auto issue = [&](int kt, int st) {
            __nv_bfloat16* s = sm + FL_ST0 + st * FL_STAGE;
            #pragma unroll
            for (int r = 0; r < 2; r++) {
                int row = row_c + r * 64;
                size_t go = ((size_t)g * GS + kt * 128 + row) * 128 + h * 32 + seg_c;
                int so = row * LDS_ + seg_c;
                CP16(smem_u32(s + FL_KH + so), KH + go);
                CP16(smem_u32(s + FL_KL + so), KL + go);
                CP16(smem_u32(s + FL_VH + so), VH + go);
                CP16(smem_u32(s + FL_VL + so), VL + go);
            }
            CP_COMMIT();
        };

        {
            #pragma unroll
            for (int r = 0; r < 2; r++) {
                int row = row_c + r * 64;
                size_t go = ((size_t)g * GS + qt * 128 + row) * 128 + h * 32 + seg_c;
                int so = row * LDS_ + seg_c;
                CP16(smem_u32(sm + FL_QH + so), QH + go);
                CP16(smem_u32(sm + FL_QL + so), QL + go);
            }
            __nv_bfloat16* s = sm + FL_ST0;
            #pragma unroll
            for (int r = 0; r < 2; r++) {
                int row = row_c + r * 64;
                size_t go = ((size_t)g * GS + row) * 128 + h * 32 + seg_c;
                int so = row * LDS_ + seg_c;
                CP16(smem_u32(s + FL_KH + so), KH + go);
                CP16(smem_u32(s + FL_KL + so), KL + go);
                CP16(smem_u32(s + FL_VH + so), VH + go);
                CP16(smem_u32(s + FL_VL + so), VL + go);
            }
            CP_COMMIT();
        }
        issue(1, 1);

        uint32_t qh_[2][4], ql_[2][4];
        float m0 = -1e30f, m1 = -1e30f, l0 = 0.f, l1 = 0.f;
        float O[4][4];
        #pragma unroll
        for (int n = 0; n < 4; n++)
            #pragma unroll
            for (int j = 0; j < 4; j++) O[n][j] = 0.f;

        const float scale = 0.088388347648318447f;

        for (int kt = 0; kt < 4; kt++) {
            if (kt < 3) CP_WAIT1(); else CP_WAIT0();
            __syncthreads();
            const __nv_bfloat16* s = sm + FL_ST0 + (kt & 1) * FL_STAGE;

            if (kt == 0) {
                #pragma unroll
                for (int kf = 0; kf < 2; kf++) {
                    int row = warp * 16 + (lane & 15);
                    int col = kf * 16 + (lane >> 4) * 8;
                    LDMX4(qh_[kf], smem_u32(sm + FL_QH + row * LDS_ + col));
                    LDMX4(ql_[kf], smem_u32(sm + FL_QL + row * LDS_ + col));
                }
            }

            float S[16][4];
            #pragma unroll
            for (int j = 0; j < 16; j++)
                #pragma unroll
                for (int r = 0; r < 4; r++) S[j][r] = 0.f;
            {
                int brow = ((lane >> 4) & 1) * 8 + (lane & 7);
                #pragma unroll
                for (int jp = 0; jp < 8; jp++) {
                    #pragma unroll
                    for (int kf = 0; kf < 2; kf++) {
                        uint32_t bh4[4], bl4[4];
                        int off = (jp * 16 + brow) * LDS_ + kf * 16 + ((lane >> 3) & 1) * 8;
                        LDMX4(bh4, smem_u32(s + FL_KH + off));
                        LDMX4(bl4, smem_u32(s + FL_KL + off));
                        MMA16816(S[2 * jp],     qh_[kf], bh4);
                        MMA16816(S[2 * jp],     ql_[kf], bh4);
                        MMA16816(S[2 * jp],     qh_[kf], bl4);
                        MMA16816(S[2 * jp + 1], qh_[kf], bh4 + 2);
                        MMA16816(S[2 * jp + 1], ql_[kf], bh4 + 2);
                        MMA16816(S[2 * jp + 1], qh_[kf], bl4 + 2);
                    }
                }
            }
            float mx0 = -1e30f, mx1 = -1e30f;
            #pragma unroll
            for (int j = 0; j < 16; j++) {
                S[j][0] *= scale; S[j][1] *= scale; S[j][2] *= scale; S[j][3] *= scale;
                mx0 = fmaxf(mx0, fmaxf(S[j][0], S[j][1]));
                mx1 = fmaxf(mx1, fmaxf(S[j][2], S[j][3]));
            }
            #pragma unroll
            for (int o = 1; o < 4; o <<= 1) {
                mx0 = fmaxf(mx0, __shfl_xor_sync(0xffffffffu, mx0, o));
                mx1 = fmaxf(mx1, __shfl_xor_sync(0xffffffffu, mx1, o));
            }
            float nm0 = fmaxf(m0, mx0), nm1 = fmaxf(m1, mx1);
            float a0 = __expf(m0 - nm0), a1 = __expf(m1 - nm1);
            float rs0 = 0.f, rs1 = 0.f;
            #pragma unroll
            for (int j = 0; j < 16; j++) {
                S[j][0] = __expf(S[j][0] - nm0); S[j][1] = __expf(S[j][1] - nm0);
                S[j][2] = __expf(S[j][2] - nm1); S[j][3] = __expf(S[j][3] - nm1);
                rs0 += S[j][0] + S[j][1];
                rs1 += S[j][2] + S[j][3];
            }
            #pragma unroll
            for (int o = 1; o < 4; o <<= 1) {
                rs0 += __shfl_xor_sync(0xffffffffu, rs0, o);
                rs1 += __shfl_xor_sync(0xffffffffu, rs1, o);
            }
            l0 = l0 * a0 + rs0;
            l1 = l1 * a1 + rs1;
            #pragma unroll
            for (int n = 0; n < 4; n++) {
                O[n][0] *= a0; O[n][1] *= a0; O[n][2] *= a1; O[n][3] *= a1;
            }
            m0 = nm0; m1 = nm1;
            #pragma unroll
            for (int jp = 0; jp < 8; jp++) {
                uint32_t aph[4], apl[4];
                split2(S[2 * jp][0],     S[2 * jp][1],     aph[0], apl[0]);
                split2(S[2 * jp][2],     S[2 * jp][3],     aph[1], apl[1]);
                split2(S[2 * jp + 1][0], S[2 * jp + 1][1], aph[2], apl[2]);
                split2(S[2 * jp + 1][2], S[2 * jp + 1][3], aph[3], apl[3]);
                int vrow = jp * 16 + ((lane >> 3) & 1) * 8 + (lane & 7);
                #pragma unroll
                for (int np = 0; np < 2; np++) {
                    uint32_t bh4[4], bl4[4];
                    int off = vrow * LDS_ + (2 * np + ((lane >> 4) & 1)) * 8;
                    LDMX4T(bh4, smem_u32(s + FL_VH + off));
                    LDMX4T(bl4, smem_u32(s + FL_VL + off));
                    MMA16816(O[2 * np],     aph, bh4);
                    MMA16816(O[2 * np],     apl, bh4);
                    MMA16816(O[2 * np],     aph, bl4);
                    MMA16816(O[2 * np + 1], aph, bh4 + 2);
                    MMA16816(O[2 * np + 1], apl, bh4 + 2);
                    MMA16816(O[2 * np + 1], aph, bl4 + 2);
                }
            }
            __syncthreads();
            if (kt + 2 < 4) issue(kt + 2, kt & 1);
        }
        float il0 = 1.f / l0, il1 = 1.f / l1;
        int node = g * GS + qt * 128 + warp * 16 + (lane >> 2);
        #pragma unroll
        for (int n = 0; n < 4; n++) {
            int col = h * 32 + n * 8 + (lane & 3) * 2;
            uint32_t hh, ll;
            split2(O[n][0] * il0, O[n][1] * il0, hh, ll);
            *(uint32_t*)(OHo + (size_t)node * 128 + col) = hh;
            *(uint32_t*)(OLo + (size_t)node * 128 + col) = ll;
            split2(O[n][2] * il1, O[n][3] * il1, hh, ll);
            *(uint32_t*)(OHo + (size_t)(node + 8) * 128 + col) = hh;
            *(uint32_t*)(OLo + (size_t)(node + 8) * 128 + col) = ll;
        }
    }
}

// ================= host orchestration =================
extern "C" void kernel_launch(void* const* d_in, const int* in_sizes, int n_in,
                              void* d_out, int out_size)
{
    const float* x   = (const float*)d_in[0];
    const int*   ei  = (const int*)  d_in[1];
    const float* W1  = (const float*)d_in[3];
    const float* a1s = (const float*)d_in[4];
    const float* a1d = (const float*)d_in[5];
    const float* b1  = (const float*)d_in[6];
    const float* W2  = (const float*)d_in[7];
    const float* a2s = (const float*)d_in[8];
    const float* a2d = (const float*)d_in[9];
    const float* b2  = (const float*)d_in[10];
    const float* W3  = (const float*)d_in[11];
    const float* a3s = (const float*)d_in[12];
    const float* a3d = (const float*)d_in[13];
    const float* b3  = (const float*)d_in[14];
    const float* g1  = (const float*)d_in[15];
    const float* be1 = (const float*)d_in[16];
    const float* g2  = (const float*)d_in[17];
    const float* be2 = (const float*)d_in[18];
    const float* Wr  = (const float*)d_in[19];
    const float* br  = (const float*)d_in[20];
    const float* Wq  = (const float*)d_in[21];
    const float* Wk  = (const float*)d_in[22];
    const float* Wv  = (const float*)d_in[23];
    const float* Wo  = (const float*)d_in[24];
    const float* bo  = (const float*)d_in[25];
    float* out = (float*)d_out;

    float* sb = nullptr;
    cudaGetSymbolAddress((void**)&sb, g_scratch);
    __nv_bfloat16* bb = nullptr;
    cudaGetSymbolAddress((void**)&bb, g_bf);
    cudaFuncSetAttribute(k_flash, cudaFuncAttributeMaxDynamicSharedMemorySize, FLASH_SMEM);
    cudaFuncSetAttribute(mma_gemm, cudaFuncAttributeMaxDynamicSharedMemorySize, GEMM_SMEM);
    cudaFuncSetAttribute(mma_gemm_qkv, cudaFuncAttributeMaxDynamicSharedMemorySize, GEMM_SMEM);

    float* p_h  = sb + OFF_H;
    float* p_h3 = sb + OFF_H3;
    float* p_r  = sb + OFF_R;
    float* p_es = sb + OFF_ES;
    float* p_ed = sb + OFF_ED;

    // conversions + g_cnt zeroing (one launch), then CSR
    k_cvt_all<<<(CVT_TOTAL + 255) / 256, 256>>>(W1, Wr, W2, W3, Wq, Wk, Wv, Wo, x);
    k_count<<<1024, 256>>>(ei);
    k_scan1<<<256, 256>>>();
    k_scan3<<<256, 256>>>();
    k_fill<<<1152, 256>>>(ei);

    // layer 1 combo: h (+H=4 scores) AND residual p_r in one GEMM (N=384)
    mma_gemm<<<PERS, 256, GEMM_SMEM>>>(bb + B_XH, bb + B_XL, bb + B_W1RH, bb + B_W1RL,
                                    nullptr, p_h, nullptr, nullptr, p_r, br,
                                    a1s, a1d, p_es, p_ed, 3, NN, 384, 64);
    k_gat_agg<256, 4><<<NN / 8, 256>>>(p_h, p_es, p_ed, b1, g1, be1, nullptr,
                                       bb + B_TH, bb + B_TL);
    // layer 2 (fused H=4 scores)
    mma_gemm<<<PERS, 256, GEMM_SMEM>>>(bb + B_TH, bb + B_TL, bb + B_W2H, bb + B_W2L,
                                    nullptr, p_h, nullptr, nullptr, nullptr, nullptr,
                                    a2s, a2d, p_es, p_ed, 1, NN, 256, 256);
    k_gat_agg<256, 4><<<NN / 8, 256>>>(p_h, p_es, p_ed, b2, g2, be2, nullptr,
                                       bb + B_TH, bb + B_TL);
    // layer 3 (fused H=1 scores)
    mma_gemm<<<PERS, 256, GEMM_SMEM>>>(bb + B_TH, bb + B_TL, bb + B_W3H, bb + B_W3L,
                                    nullptr, p_h3, nullptr, nullptr, nullptr, nullptr,
                                    a3s, a3d, p_es, p_ed, 2, NN, 128, 256);
    k_gat_agg<128, 1><<<NN / 8, 256>>>(p_h3, p_es, p_ed, b3, nullptr, nullptr, p_r,
                                       bb + B_HRH, bb + B_HRL);
    // fused QKV projection
    mma_gemm_qkv<<<PERS, 256, GEMM_SMEM>>>(bb + B_HRH, bb + B_HRL,
                                        bb + B_WQKVH, bb + B_WQKVL,
                                        bb + B_QH, bb + B_QL,
                                        bb + B_KH, bb + B_KL,
                                        bb + B_VH, bb + B_VL);
    // fused attention (persistent)
    k_flash<<<PERS, 256, FLASH_SMEM>>>(
        bb + B_QH, bb + B_QL, bb + B_KH, bb + B_KL,
        bb + B_VH, bb + B_VL, bb + B_AOH, bb + B_AOL);
    // output projection
    mma_gemm<<<PERS, 256, GEMM_SMEM>>>(bb + B_AOH, bb + B_AOL, bb + B_WOH, bb + B_WOL,
                                    bo, out, nullptr, nullptr, nullptr, nullptr,
                                    nullptr, nullptr, nullptr, nullptr, 0, NN, 128, 128);
}

// round 16
// speedup vs baseline: 1.0087x; 1.0087x over previous
#include <cuda_runtime.h>
#include <cuda_bf16.h>
#include <math.h>
#include <stdint.h>

// ---------------- problem constants ----------------
constexpr int NN   = 65536;
constexpr int NE   = 524288;
constexpr int ET   = NE + NN;
constexpr int GS   = 512;
constexpr int NG   = NN / GS;
constexpr int D1   = 256;
constexpr int D3   = 128;
constexpr int PERS = 296;   // 148 SMs x 2 CTAs

// ---------------- fp32 scratch ----------------
constexpr size_t OFF_H    = 0;
constexpr size_t OFF_H3   = OFF_H  + (size_t)NN*D1;
constexpr size_t OFF_R    = OFF_H3 + (size_t)NN*D3;
constexpr size_t OFF_ES   = OFF_R  + (size_t)NN*D3;
constexpr size_t OFF_ED   = OFF_ES + (size_t)NN*4;
constexpr size_t SCRATCH  = OFF_ED + (size_t)NN*4;

__device__ __align__(256) float g_scratch[SCRATCH];

// ---------------- bf16 scratch ----------------
constexpr size_t B_XH  = 0;
constexpr size_t B_XL  = B_XH  + (size_t)NN*64;
constexpr size_t B_TH  = B_XL  + (size_t)NN*64;
constexpr size_t B_TL  = B_TH  + (size_t)NN*256;
constexpr size_t B_HRH = B_TL  + (size_t)NN*256;
constexpr size_t B_HRL = B_HRH + (size_t)NN*128;
constexpr size_t B_AOH = B_HRL + (size_t)NN*128;
constexpr size_t B_AOL = B_AOH + (size_t)NN*128;
constexpr size_t B_QH  = B_AOL + (size_t)NN*128;
constexpr size_t B_QL  = B_QH  + (size_t)NN*128;
constexpr size_t B_KH  = B_QL  + (size_t)NN*128;
constexpr size_t B_KL  = B_KH  + (size_t)NN*128;
constexpr size_t B_VH  = B_KL  + (size_t)NN*128;
constexpr size_t B_VL  = B_VH  + (size_t)NN*128;
constexpr size_t B_W1RH = B_VL  + (size_t)NN*128;   // concat [W1;Wr]^T: 384x64
constexpr size_t B_W1RL = B_W1RH + 384*64;
constexpr size_t B_W2H = B_W1RL + 384*64;
constexpr size_t B_W2L = B_W2H + 256*256;
constexpr size_t B_W3H = B_W2L + 256*256;
constexpr size_t B_W3L = B_W3H + 128*256;
constexpr size_t B_WQKVH = B_W3L + 128*256;
constexpr size_t B_WQKVL = B_WQKVH + 384*128;
constexpr size_t B_WOH = B_WQKVL + 384*128;
constexpr size_t B_WOL = B_WOH + 128*128;
constexpr size_t BF_TOTAL = B_WOL + 128*128;

__device__ __align__(256) __nv_bfloat16 g_bf[BF_TOTAL];

__device__ int g_rowptr[NN + 1];
__device__ int g_cnt[NN];
__device__ int g_cursor[NN];
__device__ int g_col[ET];
__device__ int g_blocksum[256];

// ================= helpers =================
__device__ __forceinline__ uint32_t smem_u32(const void* p) {
    uint32_t a;
    asm("{ .reg .u64 t; cvta.to.shared.u64 t, %1; cvt.u32.u64 %0, t; }" : "=r"(a) : "l"(p));
    return a;
}
#define LDMX4(r, a) \
    asm volatile("ldmatrix.sync.aligned.m8n8.x4.shared.b16 {%0,%1,%2,%3}, [%4];" \
        : "=r"((r)[0]), "=r"((r)[1]), "=r"((r)[2]), "=r"((r)[3]) : "r"(a))
#define LDMX4T(r, a) \
    asm volatile("ldmatrix.sync.aligned.m8n8.x4.trans.shared.b16 {%0,%1,%2,%3}, [%4];" \
        : "=r"((r)[0]), "=r"((r)[1]), "=r"((r)[2]), "=r"((r)[3]) : "r"(a))
#define MMA16816(d, a, b) \
    asm volatile("mma.sync.aligned.m16n8k16.row.col.f32.bf16.bf16.f32 " \
        "{%0,%1,%2,%3}, {%4,%5,%6,%7}, {%8,%9}, {%0,%1,%2,%3};" \
        : "+f"((d)[0]), "+f"((d)[1]), "+f"((d)[2]), "+f"((d)[3]) \
        : "r"((a)[0]), "r"((a)[1]), "r"((a)[2]), "r"((a)[3]), \
          "r"((b)[0]), "r"((b)[1]))
#define CP16(dst, src) \
    asm volatile("cp.async.cg.shared.global [%0], [%1], 16;" :: "r"(dst), "l"(src))
#define CP_COMMIT() asm volatile("cp.async.commit_group;" ::: "memory")
#define CP_WAIT1()  asm volatile("cp.async.wait_group 1;" ::: "memory")
#define CP_WAIT0()  asm volatile("cp.async.wait_group 0;" ::: "memory")

__device__ __forceinline__ void split2(float v0, float v1, uint32_t& hh, uint32_t& ll) {
    __nv_bfloat16 h0 = __float2bfloat16(v0), h1 = __float2bfloat16(v1);
    __nv_bfloat16 l0 = __float2bfloat16(v0 - __bfloat162float(h0));
    __nv_bfloat16 l1 = __float2bfloat16(v1 - __bfloat162float(h1));
    __nv_bfloat162 H; H.x = h0; H.y = h1;
    __nv_bfloat162 L; L.x = l0; L.y = l1;
    hh = *(uint32_t*)&H; ll = *(uint32_t*)&L;
}

// ================= CSR build =================
__global__ void k_count(const int* __restrict__ ei) {
    int stride = gridDim.x * blockDim.x;
    for (int idx = blockIdx.x * blockDim.x + threadIdx.x; idx < NE; idx += stride)
        atomicAdd(&g_cnt[ei[NE + idx]], 1);
}
__global__ void k_scan1() {
    __shared__ int ws[8];
    int b = blockIdx.x, tid = threadIdx.x, lane = tid & 31, wid = tid >> 5;
    int v = g_cnt[b * 256 + tid] + 1;
    int x = v;
    #pragma unroll
    for (int o = 1; o < 32; o <<= 1) {
        int t = __shfl_up_sync(0xffffffffu, x, o);
        if (lane >= o) x += t;
    }
    if (lane == 31) ws[wid] = x;
    __syncthreads();
    if (tid == 0) {
        int run = 0;
        #pragma unroll
        for (int k = 0; k < 8; k++) { int t = ws[k]; ws[k] = run; run += t; }
        g_blocksum[b] = run;
    }
    __syncthreads();
    g_rowptr[b * 256 + tid] = x - v + ws[wid];
}
__global__ void k_scan3() {
    __shared__ int red[8];
    __shared__ int s_off;
    int b = blockIdx.x, tid = threadIdx.x, lane = tid & 31, wid = tid >> 5;
    int v = (tid < b) ? g_blocksum[tid] : 0;
    #pragma unroll
    for (int o = 16; o; o >>= 1) v += __shfl_xor_sync(0xffffffffu, v, o);
    if (lane == 0) red[wid] = v;
    __syncthreads();
    if (tid == 0) {
        int t = 0;
        #pragma unroll
        for (int k = 0; k < 8; k++) t += red[k];
        s_off = t;
    }
    __syncthreads();
    int idx = b * 256 + tid;
    int val = g_rowptr[idx] + s_off;
    g_rowptr[idx] = val;
    g_cursor[idx] = val;
    if (idx == 0) g_rowptr[NN] = ET;
}
__global__ void k_fill(const int* __restrict__ ei) {
    int stride = gridDim.x * blockDim.x;
    for (int idx = blockIdx.x * blockDim.x + threadIdx.x; idx < ET; idx += stride) {
        int s, d;
        if (idx < NE) { s = ei[idx]; d = ei[NE + idx]; }
        else          { s = d = idx - NE; }
        int pos = atomicAdd(&g_cursor[d], 1);
        g_col[pos] = s;
    }
}

// ============ conversions: weights + x + g_cnt zeroing in ONE launch =========
constexpr int WSEG0 = 384 * 64;                 // W1R
constexpr int WSEG1 = WSEG0 + 256 * 256;        // W2
constexpr int WSEG2 = WSEG1 + 128 * 256;        // W3
constexpr int WSEG3 = WSEG2 + 384 * 128;        // WQKV
constexpr int WSEG4 = WSEG3 + 128 * 128;        // WO
constexpr int XGROUPS = NN * 64 / 4;            // x as float4 groups
constexpr int ZSEG = NN / 4;                    // g_cnt zero as int4 groups
constexpr int CVT_TOTAL = WSEG4 + XGROUPS + ZSEG;
__global__ void k_cvt_all(const float* __restrict__ W1, const float* __restrict__ Wr,
                          const float* __restrict__ W2, const float* __restrict__ W3,
                          const float* __restrict__ Wq, const float* __restrict__ Wk,
                          const float* __restrict__ Wv, const float* __restrict__ Wo,
                          const float* __restrict__ x) {
    int idx = blockIdx.x * blockDim.x + threadIdx.x;
    if (idx >= CVT_TOTAL) return;
    if (idx >= WSEG4 + XGROUPS) {
        int i = idx - WSEG4 - XGROUPS;
        ((int4*)g_cnt)[i] = make_int4(0, 0, 0, 0);
        return;
    }
    if (idx >= WSEG4) {
        int i = idx - WSEG4;
        float4 v = ((const float4*)x)[i];
        uint32_t h01, l01, h23, l23;
        split2(v.x, v.y, h01, l01);
        split2(v.z, v.w, h23, l23);
        ((uint32_t*)(g_bf + B_XH))[2 * i] = h01;
        ((uint32_t*)(g_bf + B_XH))[2 * i + 1] = h23;
        ((uint32_t*)(g_bf + B_XL))[2 * i] = l01;
        ((uint32_t*)(g_bf + B_XL))[2 * i + 1] = l23;
        return;
    }
    float v;
    size_t hoff, loff;
    if (idx < WSEG0) {
        int li = idx, n = li / 64, k = li % 64;
        v = (n < 256) ? W1[(size_t)k * 256 + n] : Wr[(size_t)k * 128 + (n - 256)];
        hoff = B_W1RH + li; loff = B_W1RL + li;
    } else if (idx < WSEG1) {
        int li = idx - WSEG0, n = li / 256, k = li % 256;
        v = W2[(size_t)k * 256 + n];
        hoff = B_W2H + li; loff = B_W2L + li;
    } else if (idx < WSEG2) {
        int li = idx - WSEG1, n = li / 256, k = li % 256;
        v = W3[(size_t)k * 128 + n];
        hoff = B_W3H + li; loff = B_W3L + li;
    } else if (idx < WSEG3) {
        int li = idx - WSEG2, n = li / 128, k = li % 128;
        const float* W = (n < 128) ? Wq : ((n < 256) ? Wk : Wv);
        v = W[(size_t)k * 128 + (n & 127)];
        hoff = B_WQKVH + li; loff = B_WQKVL + li;
    } else {
        int li = idx - WSEG3, n = li / 128, k = li % 128;
        v = Wo[(size_t)k * 128 + n];
        hoff = B_WOH + li; loff = B_WOL + li;
    }
    __nv_bfloat16 h = __float2bfloat16(v);
    g_bf[hoff] = h;
    g_bf[loff] = __float2bfloat16(v - __bfloat162float(h));
}

// ================= mma.sync bf16-split GEMM, persistent tiles ================
constexpr int LDS_ = 40;
constexpr int G_OAL = 128 * LDS_;
constexpr int G_OBH = 2 * 128 * LDS_;
constexpr int G_OBL = 3 * 128 * LDS_;
constexpr int G_STAGE = 4 * 128 * LDS_;
constexpr int GEMM_SMEM = 2 * G_STAGE * 2;

__global__ __launch_bounds__(256, 2) void mma_gemm(
    const __nv_bfloat16* __restrict__ Ah, const __nv_bfloat16* __restrict__ Al,
    const __nv_bfloat16* __restrict__ Bh, const __nv_bfloat16* __restrict__ Bl,
    const float* __restrict__ bias, float* __restrict__ C,
    __nv_bfloat16* __restrict__ Chi, __nv_bfloat16* __restrict__ Clo,
    float* __restrict__ C2, const float* __restrict__ bias2,
    const float* __restrict__ asv, const float* __restrict__ adv,
    float* __restrict__ esv, float* __restrict__ edv_out,
    int score_mode, int M, int N, int K)
{
    extern __shared__ __nv_bfloat16 smem[];
    int tid = threadIdx.x, lane = tid & 31, warp = tid >> 5;
    int wm = warp & 3, wn = warp >> 2;
    int nbn = N >> 7;
    int ntiles = (M >> 7) * nbn;
    int row_c = tid >> 2, seg_c = (tid & 3) * 8;
    int nch = K >> 5;

    for (int tile = blockIdx.x; tile < ntiles; tile += gridDim.x) {
        int bm = tile / nbn, bn = tile - bm * nbn;
        const __nv_bfloat16* gAh = Ah + (size_t)bm * 128 * K;
        const __nv_bfloat16* gAl = Al + (size_t)bm * 128 * K;
        const __nv_bfloat16* gBh = Bh + (size_t)bn * 128 * K;
        const __nv_bfloat16* gBl = Bl + (size_t)bn * 128 * K;

        auto issue = [&](int ich, int st) {
            int k0 = ich << 5;
            __nv_bfloat16* s = smem + st * G_STAGE;
            #pragma unroll
            for (int r = 0; r < 2; r++) {
                int row = row_c + r * 64;
                size_t go = (size_t)row * K + k0 + seg_c;
                int so = row * LDS_ + seg_c;
                CP16(smem_u32(s + so), gAh + go);
                CP16(smem_u32(s + G_OAL + so), gAl + go);
                CP16(smem_u32(s + G_OBH + so), gBh + go);
                CP16(smem_u32(s + G_OBL + so), gBl + go);
            }
            CP_COMMIT();
        };

        float d[2][8][4];
        #pragma unroll
        for (int mi = 0; mi < 2; mi++)
            #pragma unroll
            for (int ni = 0; ni < 8; ni++)
                #pragma unroll
                for (int j = 0; j < 4; j++) d[mi][ni][j] = 0.f;

        issue(0, 0);
        if (nch > 1) issue(1, 1);

        for (int ich = 0; ich < nch; ich++) {
            if (ich + 1 < nch) CP_WAIT1(); else CP_WAIT0();
            __syncthreads();
            const __nv_bfloat16* s = smem + (ich & 1) * G_STAGE;
            #pragma unroll
            for (int ks = 0; ks < 2; ks++) {
                uint32_t ah[2][4], al[2][4];
                #pragma unroll
                for (int mi = 0; mi < 2; mi++) {
                    int row = wm * 32 + mi * 16 + (lane & 15);
                    int col = ks * 16 + (lane >> 4) * 8;
                    LDMX4(ah[mi], smem_u32(s + row * LDS_ + col));
                    LDMX4(al[mi], smem_u32(s + G_OAL + row * LDS_ + col));
                }
                int brow = wn * 64 + ((lane >> 4) & 1) * 8 + (lane & 7);
                int bcol = ks * 16 + ((lane >> 3) & 1) * 8;
                #pragma unroll
                for (int p = 0; p < 4; p++) {
                    uint32_t bh4[4], bl4[4];
                    int off = (brow + p * 16) * LDS_ + bcol;
                    LDMX4(bh4, smem_u32(s + G_OBH + off));
                    LDMX4(bl4, smem_u32(s + G_OBL + off));
                    #pragma unroll
                    for (int mi = 0; mi < 2; mi++) {
                        MMA16816(d[mi][2 * p],     ah[mi], bh4);
                        MMA16816(d[mi][2 * p],     al[mi], bh4);
                        MMA16816(d[mi][2 * p],     ah[mi], bl4);
                        MMA16816(d[mi][2 * p + 1], ah[mi], bh4 + 2);
                        MMA16816(d[mi][2 * p + 1], al[mi], bh4 + 2);
                        MMA16816(d[mi][2 * p + 1], ah[mi], bl4 + 2);
                    }
                }
            }
            __syncthreads();
            if (ich + 2 < nch) issue(ich + 2, ich & 1);
        }

        // epilogue
        if (score_mode == 3 && bn == 2) {
            #pragma unroll
            for (int mi = 0; mi < 2; mi++) {
                int row = bm * 128 + wm * 32 + mi * 16 + (lane >> 2);
                #pragma unroll
                for (int ni = 0; ni < 8; ni++) {
                    int col = wn * 64 + ni * 8 + (lane & 3) * 2;
                    float b0 = bias2[col], b1 = bias2[col + 1];
                    *(float2*)(C2 + (size_t)row * 128 + col) =
                        make_float2(d[mi][ni][0] + b0, d[mi][ni][1] + b1);
                    *(float2*)(C2 + (size_t)(row + 8) * 128 + col) =
                        make_float2(d[mi][ni][2] + b0, d[mi][ni][3] + b1);
                }
            }
        } else {
            int outN = (score_mode == 3) ? 256 : N;
            #pragma unroll
            for (int mi = 0; mi < 2; mi++) {
                int row = bm * 128 + wm * 32 + mi * 16 + (lane >> 2);
                #pragma unroll
                for (int ni = 0; ni < 8; ni++) {
                    int col = bn * 128 + wn * 64 + ni * 8 + (lane & 3) * 2;
                    if (C) {
                        float b0 = bias ? bias[col] : 0.f;
                        float b1 = bias ? bias[col + 1] : 0.f;
                        *(float2*)(C + (size_t)row * outN + col) =
                            make_float2(d[mi][ni][0] + b0, d[mi][ni][1] + b1);
                        *(float2*)(C + (size_t)(row + 8) * outN + col) =
                            make_float2(d[mi][ni][2] + b0, d[mi][ni][3] + b1);
                    } else {
                        uint32_t hh, ll;
                        split2(d[mi][ni][0], d[mi][ni][1], hh, ll);
                        *(uint32_t*)(Chi + (size_t)row * outN + col) = hh;
                        *(uint32_t*)(Clo + (size_t)row * outN + col) = ll;
                        split2(d[mi][ni][2], d[mi][ni][3], hh, ll);
                        *(uint32_t*)(Chi + (size_t)(row + 8) * outN + col) = hh;
                        *(uint32_t*)(Clo + (size_t)(row + 8) * outN + col) = ll;
                    }
                }
            }
        }
        if (score_mode == 1 || (score_mode == 3 && bn < 2)) {
            int hd = bn * 2 + wn;
            float sv[4] = {0.f, 0.f, 0.f, 0.f}, dv[4] = {0.f, 0.f, 0.f, 0.f};
            #pragma unroll
            for (int mi = 0; mi < 2; mi++)
                #pragma unroll
                for (int ni = 0; ni < 8; ni++)
                    #pragma unroll
                    for (int j = 0; j < 2; j++) {
                        int cl = ni * 8 + (lane & 3) * 2 + j;
                        float a = asv[hd * 64 + cl], b = adv[hd * 64 + cl];
                        sv[mi * 2]     += d[mi][ni][j]     * a;
                        dv[mi * 2]     += d[mi][ni][j]     * b;
                        sv[mi * 2 + 1] += d[mi][ni][2 + j] * a;
                        dv[mi * 2 + 1] += d[mi][ni][2 + j] * b;
                    }
            #pragma unroll
            for (int r = 0; r < 4; r++) {
                sv[r] += __shfl_xor_sync(0xffffffffu, sv[r], 1);
                sv[r] += __shfl_xor_sync(0xffffffffu, sv[r], 2);
                dv[r] += __shfl_xor_sync(0xffffffffu, dv[r], 1);
                dv[r] += __shfl_xor_sync(0xffffffffu, dv[r], 2);
            }
            if ((lane & 3) == 0) {
                #pragma unroll
                for (int r = 0; r < 4; r++) {
                    int row = bm * 128 + wm * 32 + (r >> 1) * 16 + (lane >> 2) + (r & 1) * 8;
                    esv[(size_t)row * 4 + hd]     = sv[r];
                    edv_out[(size_t)row * 4 + hd] = dv[r];
                }
            }
        } else if (score_mode == 2) {
            float* reds = (float*)smem;
            float* redd = reds + 256;
            float sv[4] = {0.f, 0.f, 0.f, 0.f}, dv[4] = {0.f, 0.f, 0.f, 0.f};
            #pragma unroll
            for (int mi = 0; mi < 2; mi++)
                #pragma unroll
                for (int ni = 0; ni < 8; ni++)
                    #pragma unroll
                    for (int j = 0; j < 2; j++) {
                        int cl = wn * 64 + ni * 8 + (lane & 3) * 2 + j;
                        float a = asv[cl], b = adv[cl];
                        sv[mi * 2]     += d[mi][ni][j]     * a;
                        dv[mi * 2]     += d[mi][ni][j]     * b;
                        sv[mi * 2 + 1] += d[mi][ni][2 + j] * a;
                        dv[mi * 2 + 1] += d[mi][ni][2 + j] * b;
                    }
            #pragma unroll
            for (int r = 0; r < 4; r++) {
                sv[r] += __shfl_xor_sync(0xffffffffu, sv[r], 1);
                sv[r] += __shfl_xor_sync(0xffffffffu, sv[r], 2);
                dv[r] += __shfl_xor_sync(0xffffffffu, dv[r], 1);
                dv[r] += __shfl_xor_sync(0xffffffffu, dv[r], 2);
            }
            __syncthreads();
            if ((lane & 3) == 0) {
                #pragma unroll
                for (int r = 0; r < 4; r++) {
                    int row = wm * 32 + (r >> 1) * 16 + (lane >> 2) + (r & 1) * 8;
                    reds[row * 2 + wn] = sv[r];
                    redd[row * 2 + wn] = dv[r];
                }
            }
            __syncthreads();
            if (tid < 128) {
                esv[(size_t)(bm * 128 + tid)]     = reds[tid * 2] + reds[tid * 2 + 1];
                edv_out[(size_t)(bm * 128 + tid)] = redd[tid * 2] + redd[tid * 2 + 1];
            }
            __syncthreads();
        }
    }
}

// ================= QKV fused GEMM (persistent) =================
__global__ __launch_bounds__(256, 2) void mma_gemm_qkv(
    const __nv_bfloat16* __restrict__ Ah, const __nv_bfloat16* __restrict__ Al,
    const __nv_bfloat16* __restrict__ Bh, const __nv_bfloat16* __restrict__ Bl,
    __nv_bfloat16* __restrict__ QH, __nv_bfloat16* __restrict__ QL,
    __nv_bfloat16* __restrict__ KH, __nv_bfloat16* __restrict__ KL,
    __nv_bfloat16* __restrict__ VH, __nv_bfloat16* __restrict__ VL)
{
    constexpr int K = 128;
    constexpr int nch = K >> 5;
    extern __shared__ __nv_bfloat16 smem[];
    int tid = threadIdx.x, lane = tid & 31, warp = tid >> 5;
    int wm = warp & 3, wn = warp >> 2;
    int row_c = tid >> 2, seg_c = (tid & 3) * 8;
    constexpr int ntiles = 3 * 512;

    for (int tile = blockIdx.x; tile < ntiles; tile += gridDim.x) {
        int bm = tile / 3, bn = tile - bm * 3;
        const __nv_bfloat16* gAh = Ah + (size_t)bm * 128 * K;
        const __nv_bfloat16* gAl = Al + (size_t)bm * 128 * K;
        const __nv_bfloat16* gBh = Bh + (size_t)bn * 128 * K;
        const __nv_bfloat16* gBl = Bl + (size_t)bn * 128 * K;

        auto issue = [&](int ich, int st) {
            int k0 = ich << 5;
            __nv_bfloat16* s = smem + st * G_STAGE;
            #pragma unroll
            for (int r = 0; r < 2; r++) {
                int row = row_c + r * 64;
                size_t go = (size_t)row * K + k0 + seg_c;
                int so = row * LDS_ + seg_c;
                CP16(smem_u32(s + so), gAh + go);
                CP16(smem_u32(s + G_OAL + so), gAl + go);
                CP16(smem_u32(s + G_OBH + so), gBh + go);
                CP16(smem_u32(s + G_OBL + so), gBl + go);
            }
            CP_COMMIT();
        };

        float d[2][8][4];
        #pragma unroll
        for (int mi = 0; mi < 2; mi++)
            #pragma unroll
            for (int ni = 0; ni < 8; ni++)
                #pragma unroll
                for (int j = 0; j < 4; j++) d[mi][ni][j] = 0.f;

        issue(0, 0);
        issue(1, 1);
        for (int ich = 0; ich < nch; ich++) {
            if (ich + 1 < nch) CP_WAIT1(); else CP_WAIT0();
            __syncthreads();
            const __nv_bfloat16* s = smem + (ich & 1) * G_STAGE;
            #pragma unroll
            for (int ks = 0; ks < 2; ks++) {
                uint32_t ah[2][4], al[2][4];
                #pragma unroll
                for (int mi = 0; mi < 2; mi++) {
                    int row = wm * 32 + mi * 16 + (lane & 15);
                    int col = ks * 16 + (lane >> 4) * 8;
                    LDMX4(ah[mi], smem_u32(s + row * LDS_ + col));
                    LDMX4(al[mi], smem_u32(s + G_OAL + row * LDS_ + col));
                }
                int brow = wn * 64 + ((lane >> 4) & 1) * 8 + (lane & 7);
                int bcol = ks * 16 + ((lane >> 3) & 1) * 8;
                #pragma unroll
                for (int p = 0; p < 4; p++) {
                    uint32_t bh4[4], bl4[4];
                    int off = (brow + p * 16) * LDS_ + bcol;
                    LDMX4(bh4, smem_u32(s + G_OBH + off));
                    LDMX4(bl4, smem_u32(s + G_OBL + off));
                    #pragma unroll
                    for (int mi = 0; mi < 2; mi++) {
                        MMA16816(d[mi][2 * p],     ah[mi], bh4);
                        MMA16816(d[mi][2 * p],     al[mi], bh4);
                        MMA16816(d[mi][2 * p],     ah[mi], bl4);
                        MMA16816(d[mi][2 * p + 1], ah[mi], bh4 + 2);
                        MMA16816(d[mi][2 * p + 1], al[mi], bh4 + 2);
                        MMA16816(d[mi][2 * p + 1], ah[mi], bl4 + 2);
                    }
                }
            }
            __syncthreads();
            if (ich + 2 < nch) issue(ich + 2, ich & 1);
        }
        __nv_bfloat16 *Oh, *Ol;
        if (bn == 0)      { Oh = QH; Ol = QL; }
        else if (bn == 1) { Oh = KH; Ol = KL; }
        else              { Oh = VH; Ol = VL; }
        #pragma unroll
        for (int mi = 0; mi < 2; mi++) {
            int row = bm * 128 + wm * 32 + mi * 16 + (lane >> 2);
            #pragma unroll
            for (int ni = 0; ni < 8; ni++) {
                int col = wn * 64 + ni * 8 + (lane & 3) * 2;
                uint32_t hh, ll;
                split2(d[mi][ni][0], d[mi][ni][1], hh, ll);
                *(uint32_t*)(Oh + (size_t)row * 128 + col) = hh;
                *(uint32_t*)(Ol + (size_t)row * 128 + col) = ll;
                split2(d[mi][ni][2], d[mi][ni][3], hh, ll);
                *(uint32_t*)(Oh + (size_t)(row + 8) * 128 + col) = hh;
                *(uint32_t*)(Ol + (size_t)(row + 8) * 128 + col) = ll;
            }
        }
    }
}

// ================= GAT aggregation — single pass, float4 vectorized ==========
template <int D, int H>
__global__ __launch_bounds__(256) void k_gat_agg(
    const float* __restrict__ hfeat, const float* __restrict__ es,
    const float* __restrict__ ed, const float* __restrict__ bias,
    const float* __restrict__ gamma, const float* __restrict__ beta,
    const float* __restrict__ resid,
    __nv_bfloat16* __restrict__ outH, __nv_bfloat16* __restrict__ outL)
{
    constexpr int C = D / H;
    constexpr int NV = D / 128;
    int warp = (blockIdx.x * blockDim.x + threadIdx.x) >> 5;
    int lane = threadIdx.x & 31;
    if (warp >= NN) return;
    int i = warp;
    int beg = g_rowptr[i], end = g_rowptr[i + 1];

    float edv[H], z[H];
    #pragma unroll
    for (int h = 0; h < H; h++) {
        edv[h] = ed[(size_t)i * H + h];
        z[h] = 0.f;
    }
    float4 acc[NV];
    #pragma unroll
    for (int j = 0; j < NV; j++) acc[j] = make_float4(0.f, 0.f, 0.f, 0.f);

    for (int e = beg; e < end; e++) {
        int s = g_col[e];
        float al[H];
        if (H == 4) {
            float4 ev = ((const float4*)es)[s];
            float vv[4] = {ev.x, ev.y, ev.z, ev.w};
            #pragma unroll
            for (int h = 0; h < 4; h++) {
                float v = vv[h] + edv[h];
                v = v > 0.f ? v : 0.2f * v;
                al[h] = __expf(v);
                z[h] += al[h];
            }
        } else {
            float v = es[s] + edv[0];
            v = v > 0.f ? v : 0.2f * v;
            al[0] = __expf(v);
            z[0] += al[0];
        }
        const float4* hs = (const float4*)(hfeat + (size_t)s * D);
        #pragma unroll
        for (int j = 0; j < NV; j++) {
            float4 hv = hs[lane + 32 * j];
            float a = (H == 1) ? al[0] : al[((lane + 32 * j) * 4) / C];
            acc[j].x += a * hv.x; acc[j].y += a * hv.y;
            acc[j].z += a * hv.z; acc[j].w += a * hv.w;
        }
    }
    #pragma unroll
    for (int h = 0; h < H; h++) z[h] = 1.f / (z[h] + 1e-16f);

    float4 x[NV];
    #pragma unroll
    for (int j = 0; j < NV; j++) {
        int g4 = lane + 32 * j;
        float zz = (H == 1) ? z[0] : z[(g4 * 4) / C];
        float4 b4 = ((const float4*)bias)[g4];
        x[j].x = acc[j].x * zz + b4.x;
        x[j].y = acc[j].y * zz + b4.y;
        x[j].z = acc[j].z * zz + b4.z;
        x[j].w = acc[j].w * zz + b4.w;
        if (resid) {
            float4 r4 = ((const float4*)(resid + (size_t)i * D))[g4];
            x[j].x += r4.x; x[j].y += r4.y; x[j].z += r4.z; x[j].w += r4.w;
        }
    }
    if (gamma) {
        #pragma unroll
        for (int j = 0; j < NV; j++) {
            x[j].x = x[j].x > 0.f ? x[j].x : (__expf(x[j].x) - 1.f);
            x[j].y = x[j].y > 0.f ? x[j].y : (__expf(x[j].y) - 1.f);
            x[j].z = x[j].z > 0.f ? x[j].z : (__expf(x[j].z) - 1.f);
            x[j].w = x[j].w > 0.f ? x[j].w : (__expf(x[j].w) - 1.f);
        }
        float s = 0.f;
        #pragma unroll
        for (int j = 0; j < NV; j++) s += x[j].x + x[j].y + x[j].z + x[j].w;
        #pragma unroll
        for (int o = 16; o; o >>= 1) s += __shfl_xor_sync(0xffffffffu, s, o);
        float mu = s / (float)D;
        float vs = 0.f;
        #pragma unroll
        for (int j = 0; j < NV; j++) {
            float a = x[j].x - mu, b = x[j].y - mu, c = x[j].z - mu, dd = x[j].w - mu;
            vs += a * a + b * b + c * c + dd * dd;
        }
        #pragma unroll
        for (int o = 16; o; o >>= 1) vs += __shfl_xor_sync(0xffffffffu, vs, o);
        float inv = rsqrtf(vs / (float)D + 1e-5f);
        #pragma unroll
        for (int j = 0; j < NV; j++) {
            int g4 = lane + 32 * j;
            float4 g = ((const float4*)gamma)[g4];
            float4 be = ((const float4*)beta)[g4];
            x[j].x = (x[j].x - mu) * inv * g.x + be.x;
            x[j].y = (x[j].y - mu) * inv * g.y + be.y;
            x[j].z = (x[j].z - mu) * inv * g.z + be.z;
            x[j].w = (x[j].w - mu) * inv * g.w + be.w;
        }
    }
    #pragma unroll
    for (int j = 0; j < NV; j++) {
        int g4 = lane + 32 * j;
        uint32_t h01, l01, h23, l23;
        split2(x[j].x, x[j].y, h01, l01);
        split2(x[j].z, x[j].w, h23, l23);
        *(uint2*)(outH + (size_t)i * D + g4 * 4) = make_uint2(h01, h23);
        *(uint2*)(outL + (size_t)i * D + g4 * 4) = make_uint2(l01, l23);
    }
}

// ============ fused flash attention, cp.async K/V pipeline (non-persistent) ==
constexpr int FL_QH = 0;
constexpr int FL_QL = 128 * LDS_;
constexpr int FL_ST0 = 2 * 128 * LDS_;
constexpr int FL_KH = 0;
constexpr int FL_KL = 128 * LDS_;
constexpr int FL_VH = 2 * 128 * LDS_;
constexpr int FL_VL = 3 * 128 * LDS_;
constexpr int FL_STAGE = 4 * 128 * LDS_;
constexpr int FLASH_SMEM = (FL_ST0 + 2 * FL_STAGE) * 2;   // 102400 bytes

__global__ __launch_bounds__(256, 2) void k_flash(
    const __nv_bfloat16* __restrict__ QH, const __nv_bfloat16* __restrict__ QL,
    const __nv_bfloat16* __restrict__ KH, const __nv_bfloat16* __restrict__ KL,
    const __nv_bfloat16* __restrict__ VH, const __nv_bfloat16* __restrict__ VL,
    __nv_bfloat16* __restrict__ OHo, __nv_bfloat16* __restrict__ OLo)
{
    extern __shared__ __nv_bfloat16 sm[];
    int gh = blockIdx.y, g = gh >> 2, h = gh & 3;
    int qt = blockIdx.x;
    int tid = threadIdx.x, lane = tid & 31, warp = tid >> 5;

    int row_c = tid >> 2, seg_c = (tid & 3) * 8;

    auto issue = [&](int kt, int st) {
        __nv_bfloat16* s = sm + FL_ST0 + st * FL_STAGE;
        #pragma unroll
        for (int r = 0; r < 2; r++) {
            int row = row_c + r * 64;
            size_t go = ((size_t)g * GS + kt * 128 + row) * 128 + h * 32 + seg_c;
            int so = row * LDS_ + seg_c;
            CP16(smem_u32(s + FL_KH + so), KH + go);
            CP16(smem_u32(s + FL_KL + so), KL + go);
            CP16(smem_u32(s + FL_VH + so), VH + go);
            CP16(smem_u32(s + FL_VL + so), VL + go);
        }
        CP_COMMIT();
    };

    {
        #pragma unroll
        for (int r = 0; r < 2; r++) {
            int row = row_c + r * 64;
            size_t go = ((size_t)g * GS + qt * 128 + row) * 128 + h * 32 + seg_c;
            int so = row * LDS_ + seg_c;
            CP16(smem_u32(sm + FL_QH + so), QH + go);
            CP16(smem_u32(sm + FL_QL + so), QL + go);
        }
        __nv_bfloat16* s = sm + FL_ST0;
        #pragma unroll
        for (int r = 0; r < 2; r++) {
            int row = row_c + r * 64;
            size_t go = ((size_t)g * GS + row) * 128 + h * 32 + seg_c;
            int so = row * LDS_ + seg_c;
            CP16(smem_u32(s + FL_KH + so), KH + go);
            CP16(smem_u32(s + FL_KL + so), KL + go);
            CP16(smem_u32(s + FL_VH + so), VH + go);
            CP16(smem_u32(s + FL_VL + so), VL + go);
        }
        CP_COMMIT();
    }
    issue(1, 1);

    uint32_t qh_[2][4], ql_[2][4];
    float m0 = -1e30f, m1 = -1e30f, l0 = 0.f, l1 = 0.f;
    float O[4][4];
    #pragma unroll
    for (int n = 0; n < 4; n++)
        #pragma unroll
        for (int j = 0; j < 4; j++) O[n][j] = 0.f;

    const float scale = 0.088388347648318447f;

    for (int kt = 0; kt < 4; kt++) {
        if (kt < 3) CP_WAIT1(); else CP_WAIT0();
        __syncthreads();
        const __nv_bfloat16* s = sm + FL_ST0 + (kt & 1) * FL_STAGE;

        if (kt == 0) {
            #pragma unroll
            for (int kf = 0; kf < 2; kf++) {
                int row = warp * 16 + (lane & 15);
                int col = kf * 16 + (lane >> 4) * 8;
                LDMX4(qh_[kf], smem_u32(sm + FL_QH + row * LDS_ + col));
                LDMX4(ql_[kf], smem_u32(sm + FL_QL + row * LDS_ + col));
            }
        }

        float S[16][4];
        #pragma unroll
        for (int j = 0; j < 16; j++)
            #pragma unroll
            for (int r = 0; r < 4; r++) S[j][r] = 0.f;
        {
            int brow = ((lane >> 4) & 1) * 8 + (lane & 7);
            #pragma unroll
            for (int jp = 0; jp < 8; jp++) {
                #pragma unroll
                for (int kf = 0; kf < 2; kf++) {
                    uint32_t bh4[4], bl4[4];
                    int off = (jp * 16 + brow) * LDS_ + kf * 16 + ((lane >> 3) & 1) * 8;
                    LDMX4(bh4, smem_u32(s + FL_KH + off));
                    LDMX4(bl4, smem_u32(s + FL_KL + off));
                    MMA16816(S[2 * jp],     qh_[kf], bh4);
                    MMA16816(S[2 * jp],     ql_[kf], bh4);
                    MMA16816(S[2 * jp],     qh_[kf], bl4);
                    MMA16816(S[2 * jp + 1], qh_[kf], bh4 + 2);
                    MMA16816(S[2 * jp + 1], ql_[kf], bh4 + 2);
                    MMA16816(S[2 * jp + 1], qh_[kf], bl4 + 2);
                }
            }
        }
        float mx0 = -1e30f, mx1 = -1e30f;
        #pragma unroll
        for (int j = 0; j < 16; j++) {
            S[j][0] *= scale; S[j][1] *= scale; S[j][2] *= scale; S[j][3] *= scale;
            mx0 = fmaxf(mx0, fmaxf(S[j][0], S[j][1]));
            mx1 = fmaxf(mx1, fmaxf(S[j][2], S[j][3]));
        }
        #pragma unroll
        for (int o = 1; o < 4; o <<= 1) {
            mx0 = fmaxf(mx0, __shfl_xor_sync(0xffffffffu, mx0, o));
            mx1 = fmaxf(mx1, __shfl_xor_sync(0xffffffffu, mx1, o));
        }
        float nm0 = fmaxf(m0, mx0), nm1 = fmaxf(m1, mx1);
        float a0 = __expf(m0 - nm0), a1 = __expf(m1 - nm1);
        float rs0 = 0.f, rs1 = 0.f;
        #pragma unroll
        for (int j = 0; j < 16; j++) {
            S[j][0] = __expf(S[j][0] - nm0); S[j][1] = __expf(S[j][1] - nm0);
            S[j][2] = __expf(S[j][2] - nm1); S[j][3] = __expf(S[j][3] - nm1);
            rs0 += S[j][0] + S[j][1];
            rs1 += S[j][2] + S[j][3];
        }
        #pragma unroll
        for (int o = 1; o < 4; o <<= 1) {
            rs0 += __shfl_xor_sync(0xffffffffu, rs0, o);
            rs1 += __shfl_xor_sync(0xffffffffu, rs1, o);
        }
        l0 = l0 * a0 + rs0;
        l1 = l1 * a1 + rs1;
        #pragma unroll
        for (int n = 0; n < 4; n++) {
            O[n][0] *= a0; O[n][1] *= a0; O[n][2] *= a1; O[n][3] *= a1;
        }
        m0 = nm0; m1 = nm1;
        #pragma unroll
        for (int jp = 0; jp < 8; jp++) {
            uint32_t aph[4], apl[4];
            split2(S[2 * jp][0],     S[2 * jp][1],     aph[0], apl[0]);
            split2(S[2 * jp][2],     S[2 * jp][3],     aph[1], apl[1]);
            split2(S[2 * jp + 1][0], S[2 * jp + 1][1], aph[2], apl[2]);
            split2(S[2 * jp + 1][2], S[2 * jp + 1][3], aph[3], apl[3]);
            int vrow = jp * 16 + ((lane >> 3) & 1) * 8 + (lane & 7);
            #pragma unroll
            for (int np = 0; np < 2; np++) {
                uint32_t bh4[4], bl4[4];
                int off = vrow * LDS_ + (2 * np + ((lane >> 4) & 1)) * 8;
                LDMX4T(bh4, smem_u32(s + FL_VH + off));
                LDMX4T(bl4, smem_u32(s + FL_VL + off));
                MMA16816(O[2 * np],     aph, bh4);
                MMA16816(O[2 * np],     apl, bh4);
                MMA16816(O[2 * np],     aph, bl4);
                MMA16816(O[2 * np + 1], aph, bh4 + 2);
                MMA16816(O[2 * np + 1], apl, bh4 + 2);
                MMA16816(O[2 * np + 1], aph, bl4 + 2);
            }
        }
        __syncthreads();
        if (kt + 2 < 4) issue(kt + 2, kt & 1);
    }
    float il0 = 1.f / l0, il1 = 1.f / l1;
    int node = g * GS + qt * 128 + warp * 16 + (lane >> 2);
    #pragma unroll
    for (int n = 0; n < 4; n++) {
        int col = h * 32 + n * 8 + (lane & 3) * 2;
        uint32_t hh, ll;
        split2(O[n][0] * il0, O[n][1] * il0, hh, ll);
        *(uint32_t*)(OHo + (size_t)node * 128 + col) = hh;
        *(uint32_t*)(OLo + (size_t)node * 128 + col) = ll;
        split2(O[n][2] * il1, O[n][3] * il1, hh, ll);
        *(uint32_t*)(OHo + (size_t)(node + 8) * 128 + col) = hh;
        *(uint32_t*)(OLo + (size_t)(node + 8) * 128 + col) = ll;
    }
}

// ================= host orchestration =================
extern "C" void kernel_launch(void* const* d_in, const int* in_sizes, int n_in,
                              void* d_out, int out_size)
{
    const float* x   = (const float*)d_in[0];
    const int*   ei  = (const int*)  d_in[1];
    const float* W1  = (const float*)d_in[3];
    const float* a1s = (const float*)d_in[4];
    const float* a1d = (const float*)d_in[5];
    const float* b1  = (const float*)d_in[6];
    const float* W2  = (const float*)d_in[7];
    const float* a2s = (const float*)d_in[8];
    const float* a2d = (const float*)d_in[9];
    const float* b2  = (const float*)d_in[10];
    const float* W3  = (const float*)d_in[11];
    const float* a3s = (const float*)d_in[12];
    const float* a3d = (const float*)d_in[13];
    const float* b3  = (const float*)d_in[14];
    const float* g1  = (const float*)d_in[15];
    const float* be1 = (const float*)d_in[16];
    const float* g2  = (const float*)d_in[17];
    const float* be2 = (const float*)d_in[18];
    const float* Wr  = (const float*)d_in[19];
    const float* br  = (const float*)d_in[20];
    const float* Wq  = (const float*)d_in[21];
    const float* Wk  = (const float*)d_in[22];
    const float* Wv  = (const float*)d_in[23];
    const float* Wo  = (const float*)d_in[24];
    const float* bo  = (const float*)d_in[25];
    float* out = (float*)d_out;

    float* sb = nullptr;
    cudaGetSymbolAddress((void**)&sb, g_scratch);
    __nv_bfloat16* bb = nullptr;
    cudaGetSymbolAddress((void**)&bb, g_bf);
    cudaFuncSetAttribute(k_flash, cudaFuncAttributeMaxDynamicSharedMemorySize, FLASH_SMEM);
    cudaFuncSetAttribute(mma_gemm, cudaFuncAttributeMaxDynamicSharedMemorySize, GEMM_SMEM);
    cudaFuncSetAttribute(mma_gemm_qkv, cudaFuncAttributeMaxDynamicSharedMemorySize, GEMM_SMEM);

    float* p_h  = sb + OFF_H;
    float* p_h3 = sb + OFF_H3;
    float* p_r  = sb + OFF_R;
    float* p_es = sb + OFF_ES;
    float* p_ed = sb + OFF_ED;

    // conversions + g_cnt zeroing (one launch), then CSR
    k_cvt_all<<<(CVT_TOTAL + 255) / 256, 256>>>(W1, Wr, W2, W3, Wq, Wk, Wv, Wo, x);
    k_count<<<1024, 256>>>(ei);
    k_scan1<<<256, 256>>>();
    k_scan3<<<256, 256>>>();
    k_fill<<<1152, 256>>>(ei);

    // layer 1 combo: h (+H=4 scores) AND residual p_r in one GEMM (N=384)
    mma_gemm<<<PERS, 256, GEMM_SMEM>>>(bb + B_XH, bb + B_XL, bb + B_W1RH, bb + B_W1RL,
                                    nullptr, p_h, nullptr, nullptr, p_r, br,
                                    a1s, a1d, p_es, p_ed, 3, NN, 384, 64);
    k_gat_agg<256, 4><<<NN / 8, 256>>>(p_h, p_es, p_ed, b1, g1, be1, nullptr,
                                       bb + B_TH, bb + B_TL);
    // layer 2 (fused H=4 scores)
    mma_gemm<<<PERS, 256, GEMM_SMEM>>>(bb + B_TH, bb + B_TL, bb + B_W2H, bb + B_W2L,
                                    nullptr, p_h, nullptr, nullptr, nullptr, nullptr,
                                    a2s, a2d, p_es, p_ed, 1, NN, 256, 256);
    k_gat_agg<256, 4><<<NN / 8, 256>>>(p_h, p_es, p_ed, b2, g2, be2, nullptr,
                                       bb + B_TH, bb + B_TL);
    // layer 3 (fused H=1 scores)
    mma_gemm<<<PERS, 256, GEMM_SMEM>>>(bb + B_TH, bb + B_TL, bb + B_W3H, bb + B_W3L,
                                    nullptr, p_h3, nullptr, nullptr, nullptr, nullptr,
                                    a3s, a3d, p_es, p_ed, 2, NN, 128, 256);
    k_gat_agg<128, 1><<<NN / 8, 256>>>(p_h3, p_es, p_ed, b3, nullptr, nullptr, p_r,
                                       bb + B_HRH, bb + B_HRL);
    // fused QKV projection
    mma_gemm_qkv<<<PERS, 256, GEMM_SMEM>>>(bb + B_HRH, bb + B_HRL,
                                        bb + B_WQKVH, bb + B_WQKVL,
                                        bb + B_QH, bb + B_QL,
                                        bb + B_KH, bb + B_KL,
                                        bb + B_VH, bb + B_VL);
    // fused attention (non-persistent — best measured config)
    k_flash<<<dim3(4, NG * 4), 256, FLASH_SMEM>>>(
        bb + B_QH, bb + B_QL, bb + B_KH, bb + B_KL,
        bb + B_VH, bb + B_VL, bb + B_AOH, bb + B_AOL);
    // output projection
    mma_gemm<<<PERS, 256, GEMM_SMEM>>>(bb + B_AOH, bb + B_AOL, bb + B_WOH, bb + B_WOL,
                                    bo, out, nullptr, nullptr, nullptr, nullptr,
                                    nullptr, nullptr, nullptr, nullptr, 0, NN, 128, 128);
}

// round 17
// speedup vs baseline: 1.0111x; 1.0024x over previous
#include <cuda_runtime.h>
#include <cuda_bf16.h>
#include <math.h>
#include <stdint.h>

// ---------------- problem constants ----------------
constexpr int NN   = 65536;
constexpr int NE   = 524288;
constexpr int ET   = NE + NN;
constexpr int GS   = 512;
constexpr int NG   = NN / GS;
constexpr int D1   = 256;
constexpr int D3   = 128;
constexpr int PERS = 296;   // 148 SMs x 2 CTAs

// ---------------- fp32 scratch ----------------
constexpr size_t OFF_H    = 0;
constexpr size_t OFF_H3   = OFF_H  + (size_t)NN*D1;
constexpr size_t OFF_R    = OFF_H3 + (size_t)NN*D3;
constexpr size_t OFF_ES   = OFF_R  + (size_t)NN*D3;
constexpr size_t OFF_ED   = OFF_ES + (size_t)NN*4;
constexpr size_t SCRATCH  = OFF_ED + (size_t)NN*4;

__device__ __align__(256) float g_scratch[SCRATCH];

// ---------------- bf16 scratch ----------------
constexpr size_t B_XH  = 0;
constexpr size_t B_XL  = B_XH  + (size_t)NN*64;
constexpr size_t B_TH  = B_XL  + (size_t)NN*64;
constexpr size_t B_TL  = B_TH  + (size_t)NN*256;
constexpr size_t B_HRH = B_TL  + (size_t)NN*256;
constexpr size_t B_HRL = B_HRH + (size_t)NN*128;
constexpr size_t B_AOH = B_HRL + (size_t)NN*128;
constexpr size_t B_AOL = B_AOH + (size_t)NN*128;
constexpr size_t B_QH  = B_AOL + (size_t)NN*128;
constexpr size_t B_QL  = B_QH  + (size_t)NN*128;
constexpr size_t B_KH  = B_QL  + (size_t)NN*128;
constexpr size_t B_KL  = B_KH  + (size_t)NN*128;
constexpr size_t B_VH  = B_KL  + (size_t)NN*128;
constexpr size_t B_VL  = B_VH  + (size_t)NN*128;
constexpr size_t B_W1RH = B_VL  + (size_t)NN*128;   // concat [W1;Wr]^T: 384x64
constexpr size_t B_W1RL = B_W1RH + 384*64;
constexpr size_t B_W2H = B_W1RL + 384*64;
constexpr size_t B_W2L = B_W2H + 256*256;
constexpr size_t B_W3H = B_W2L + 256*256;
constexpr size_t B_W3L = B_W3H + 128*256;
constexpr size_t B_WQKVH = B_W3L + 128*256;
constexpr size_t B_WQKVL = B_WQKVH + 384*128;
constexpr size_t B_WOH = B_WQKVL + 384*128;
constexpr size_t B_WOL = B_WOH + 128*128;
constexpr size_t BF_TOTAL = B_WOL + 128*128;

__device__ __align__(256) __nv_bfloat16 g_bf[BF_TOTAL];

__device__ int g_rowptr[NN + 1];
__device__ int g_cnt[NN];
__device__ int g_cursor[NN];
__device__ int g_col[ET];
__device__ int g_blocksum[256];

// ================= helpers =================
__device__ __forceinline__ uint32_t smem_u32(const void* p) {
    uint32_t a;
    asm("{ .reg .u64 t; cvta.to.shared.u64 t, %1; cvt.u32.u64 %0, t; }" : "=r"(a) : "l"(p));
    return a;
}
#define LDMX4(r, a) \
    asm volatile("ldmatrix.sync.aligned.m8n8.x4.shared.b16 {%0,%1,%2,%3}, [%4];" \
        : "=r"((r)[0]), "=r"((r)[1]), "=r"((r)[2]), "=r"((r)[3]) : "r"(a))
#define LDMX4T(r, a) \
    asm volatile("ldmatrix.sync.aligned.m8n8.x4.trans.shared.b16 {%0,%1,%2,%3}, [%4];" \
        : "=r"((r)[0]), "=r"((r)[1]), "=r"((r)[2]), "=r"((r)[3]) : "r"(a))
#define MMA16816(d, a, b) \
    asm volatile("mma.sync.aligned.m16n8k16.row.col.f32.bf16.bf16.f32 " \
        "{%0,%1,%2,%3}, {%4,%5,%6,%7}, {%8,%9}, {%0,%1,%2,%3};" \
        : "+f"((d)[0]), "+f"((d)[1]), "+f"((d)[2]), "+f"((d)[3]) \
        : "r"((a)[0]), "r"((a)[1]), "r"((a)[2]), "r"((a)[3]), \
          "r"((b)[0]), "r"((b)[1]))
#define CP16(dst, src) \
    asm volatile("cp.async.cg.shared.global [%0], [%1], 16;" :: "r"(dst), "l"(src))
#define CP_COMMIT() asm volatile("cp.async.commit_group;" ::: "memory")
#define CP_WAIT1()  asm volatile("cp.async.wait_group 1;" ::: "memory")
#define CP_WAIT0()  asm volatile("cp.async.wait_group 0;" ::: "memory")

__device__ __forceinline__ void split2(float v0, float v1, uint32_t& hh, uint32_t& ll) {
    __nv_bfloat16 h0 = __float2bfloat16(v0), h1 = __float2bfloat16(v1);
    __nv_bfloat16 l0 = __float2bfloat16(v0 - __bfloat162float(h0));
    __nv_bfloat16 l1 = __float2bfloat16(v1 - __bfloat162float(h1));
    __nv_bfloat162 H; H.x = h0; H.y = h1;
    __nv_bfloat162 L; L.x = l0; L.y = l1;
    hh = *(uint32_t*)&H; ll = *(uint32_t*)&L;
}

// ================= CSR build (vectorized edge reads) =================
__global__ void k_count(const int* __restrict__ ei) {
    int i = blockIdx.x * blockDim.x + threadIdx.x;
    if (i >= NE / 4) return;
    int4 d4 = ((const int4*)(ei + NE))[i];
    atomicAdd(&g_cnt[d4.x], 1);
    atomicAdd(&g_cnt[d4.y], 1);
    atomicAdd(&g_cnt[d4.z], 1);
    atomicAdd(&g_cnt[d4.w], 1);
}
__global__ void k_scan1() {
    __shared__ int ws[8];
    int b = blockIdx.x, tid = threadIdx.x, lane = tid & 31, wid = tid >> 5;
    int v = g_cnt[b * 256 + tid] + 1;
    int x = v;
    #pragma unroll
    for (int o = 1; o < 32; o <<= 1) {
        int t = __shfl_up_sync(0xffffffffu, x, o);
        if (lane >= o) x += t;
    }
    if (lane == 31) ws[wid] = x;
    __syncthreads();
    if (tid == 0) {
        int run = 0;
        #pragma unroll
        for (int k = 0; k < 8; k++) { int t = ws[k]; ws[k] = run; run += t; }
        g_blocksum[b] = run;
    }
    __syncthreads();
    g_rowptr[b * 256 + tid] = x - v + ws[wid];
}
__global__ void k_scan3() {
    __shared__ int red[8];
    __shared__ int s_off;
    int b = blockIdx.x, tid = threadIdx.x, lane = tid & 31, wid = tid >> 5;
    int v = (tid < b) ? g_blocksum[tid] : 0;
    #pragma unroll
    for (int o = 16; o; o >>= 1) v += __shfl_xor_sync(0xffffffffu, v, o);
    if (lane == 0) red[wid] = v;
    __syncthreads();
    if (tid == 0) {
        int t = 0;
        #pragma unroll
        for (int k = 0; k < 8; k++) t += red[k];
        s_off = t;
    }
    __syncthreads();
    int idx = b * 256 + tid;
    int val = g_rowptr[idx] + s_off;
    g_rowptr[idx] = val;
    g_cursor[idx] = val;
    if (idx == 0) g_rowptr[NN] = ET;
}
// vectorized fill: threads [0, NE/4) handle 4 edges; [NE/4, NE/4+NN/4) handle 4 self-loops
constexpr int FILL_THREADS = NE / 4 + NN / 4;
__global__ void k_fill(const int* __restrict__ ei) {
    int i = blockIdx.x * blockDim.x + threadIdx.x;
    if (i >= FILL_THREADS) return;
    if (i < NE / 4) {
        int4 s4 = ((const int4*)ei)[i];
        int4 d4 = ((const int4*)(ei + NE))[i];
        g_col[atomicAdd(&g_cursor[d4.x], 1)] = s4.x;
        g_col[atomicAdd(&g_cursor[d4.y], 1)] = s4.y;
        g_col[atomicAdd(&g_cursor[d4.z], 1)] = s4.z;
        g_col[atomicAdd(&g_cursor[d4.w], 1)] = s4.w;
    } else {
        int n0 = (i - NE / 4) * 4;
        #pragma unroll
        for (int k = 0; k < 4; k++) {
            int n = n0 + k;
            g_col[atomicAdd(&g_cursor[n], 1)] = n;
        }
    }
}

// ============ conversions: weights + x + g_cnt zeroing in ONE launch =========
constexpr int WSEG0 = 384 * 64;                 // W1R
constexpr int WSEG1 = WSEG0 + 256 * 256;        // W2
constexpr int WSEG2 = WSEG1 + 128 * 256;        // W3
constexpr int WSEG3 = WSEG2 + 384 * 128;        // WQKV
constexpr int WSEG4 = WSEG3 + 128 * 128;        // WO
constexpr int XGROUPS = NN * 64 / 4;            // x as float4 groups
constexpr int ZSEG = NN / 4;                    // g_cnt zero as int4 groups
constexpr int CVT_TOTAL = WSEG4 + XGROUPS + ZSEG;
__global__ void k_cvt_all(const float* __restrict__ W1, const float* __restrict__ Wr,
                          const float* __restrict__ W2, const float* __restrict__ W3,
                          const float* __restrict__ Wq, const float* __restrict__ Wk,
                          const float* __restrict__ Wv, const float* __restrict__ Wo,
                          const float* __restrict__ x) {
    int idx = blockIdx.x * blockDim.x + threadIdx.x;
    if (idx >= CVT_TOTAL) return;
    if (idx >= WSEG4 + XGROUPS) {
        int i = idx - WSEG4 - XGROUPS;
        ((int4*)g_cnt)[i] = make_int4(0, 0, 0, 0);
        return;
    }
    if (idx >= WSEG4) {
        int i = idx - WSEG4;
        float4 v = ((const float4*)x)[i];
        uint32_t h01, l01, h23, l23;
        split2(v.x, v.y, h01, l01);
        split2(v.z, v.w, h23, l23);
        ((uint32_t*)(g_bf + B_XH))[2 * i] = h01;
        ((uint32_t*)(g_bf + B_XH))[2 * i + 1] = h23;
        ((uint32_t*)(g_bf + B_XL))[2 * i] = l01;
        ((uint32_t*)(g_bf + B_XL))[2 * i + 1] = l23;
        return;
    }
    float v;
    size_t hoff, loff;
    if (idx < WSEG0) {
        int li = idx, n = li / 64, k = li % 64;
        v = (n < 256) ? W1[(size_t)k * 256 + n] : Wr[(size_t)k * 128 + (n - 256)];
        hoff = B_W1RH + li; loff = B_W1RL + li;
    } else if (idx < WSEG1) {
        int li = idx - WSEG0, n = li / 256, k = li % 256;
        v = W2[(size_t)k * 256 + n];
        hoff = B_W2H + li; loff = B_W2L + li;
    } else if (idx < WSEG2) {
        int li = idx - WSEG1, n = li / 256, k = li % 256;
        v = W3[(size_t)k * 128 + n];
        hoff = B_W3H + li; loff = B_W3L + li;
    } else if (idx < WSEG3) {
        int li = idx - WSEG2, n = li / 128, k = li % 128;
        const float* W = (n < 128) ? Wq : ((n < 256) ? Wk : Wv);
        v = W[(size_t)k * 128 + (n & 127)];
        hoff = B_WQKVH + li; loff = B_WQKVL + li;
    } else {
        int li = idx - WSEG3, n = li / 128, k = li % 128;
        v = Wo[(size_t)k * 128 + n];
        hoff = B_WOH + li; loff = B_WOL + li;
    }
    __nv_bfloat16 h = __float2bfloat16(v);
    g_bf[hoff] = h;
    g_bf[loff] = __float2bfloat16(v - __bfloat162float(h));
}

// ================= mma.sync bf16-split GEMM, persistent tiles ================
constexpr int LDS_ = 40;
constexpr int G_OAL = 128 * LDS_;
constexpr int G_OBH = 2 * 128 * LDS_;
constexpr int G_OBL = 3 * 128 * LDS_;
constexpr int G_STAGE = 4 * 128 * LDS_;
constexpr int GEMM_SMEM = 2 * G_STAGE * 2;

__global__ __launch_bounds__(256, 2) void mma_gemm(
    const __nv_bfloat16* __restrict__ Ah, const __nv_bfloat16* __restrict__ Al,
    const __nv_bfloat16* __restrict__ Bh, const __nv_bfloat16* __restrict__ Bl,
    const float* __restrict__ bias, float* __restrict__ C,
    __nv_bfloat16* __restrict__ Chi, __nv_bfloat16* __restrict__ Clo,
    float* __restrict__ C2, const float* __restrict__ bias2,
    const float* __restrict__ asv, const float* __restrict__ adv,
    float* __restrict__ esv, float* __restrict__ edv_out,
    int score_mode, int M, int N, int K)
{
    extern __shared__ __nv_bfloat16 smem[];
    int tid = threadIdx.x, lane = tid & 31, warp = tid >> 5;
    int wm = warp & 3, wn = warp >> 2;
    int nbn = N >> 7;
    int ntiles = (M >> 7) * nbn;
    int row_c = tid >> 2, seg_c = (tid & 3) * 8;
    int nch = K >> 5;

    for (int tile = blockIdx.x; tile < ntiles; tile += gridDim.x) {
        int bm = tile / nbn, bn = tile - bm * nbn;
        const __nv_bfloat16* gAh = Ah + (size_t)bm * 128 * K;
        const __nv_bfloat16* gAl = Al + (size_t)bm * 128 * K;
        const __nv_bfloat16* gBh = Bh + (size_t)bn * 128 * K;
        const __nv_bfloat16* gBl = Bl + (size_t)bn * 128 * K;

        auto issue = [&](int ich, int st) {
            int k0 = ich << 5;
            __nv_bfloat16* s = smem + st * G_STAGE;
            #pragma unroll
            for (int r = 0; r < 2; r++) {
                int row = row_c + r * 64;
                size_t go = (size_t)row * K + k0 + seg_c;
                int so = row * LDS_ + seg_c;
                CP16(smem_u32(s + so), gAh + go);
                CP16(smem_u32(s + G_OAL + so), gAl + go);
                CP16(smem_u32(s + G_OBH + so), gBh + go);
                CP16(smem_u32(s + G_OBL + so), gBl + go);
            }
            CP_COMMIT();
        };

        float d[2][8][4];
        #pragma unroll
        for (int mi = 0; mi < 2; mi++)
            #pragma unroll
            for (int ni = 0; ni < 8; ni++)
                #pragma unroll
                for (int j = 0; j < 4; j++) d[mi][ni][j] = 0.f;

        issue(0, 0);
        if (nch > 1) issue(1, 1);

        for (int ich = 0; ich < nch; ich++) {
            if (ich + 1 < nch) CP_WAIT1(); else CP_WAIT0();
            __syncthreads();
            const __nv_bfloat16* s = smem + (ich & 1) * G_STAGE;
            #pragma unroll
            for (int ks = 0; ks < 2; ks++) {
                uint32_t ah[2][4], al[2][4];
                #pragma unroll
                for (int mi = 0; mi < 2; mi++) {
                    int row = wm * 32 + mi * 16 + (lane & 15);
                    int col = ks * 16 + (lane >> 4) * 8;
                    LDMX4(ah[mi], smem_u32(s + row * LDS_ + col));
                    LDMX4(al[mi], smem_u32(s + G_OAL + row * LDS_ + col));
                }
                int brow = wn * 64 + ((lane >> 4) & 1) * 8 + (lane & 7);
                int bcol = ks * 16 + ((lane >> 3) & 1) * 8;
                #pragma unroll
                for (int p = 0; p < 4; p++) {
                    uint32_t bh4[4], bl4[4];
                    int off = (brow + p * 16) * LDS_ + bcol;
                    LDMX4(bh4, smem_u32(s + G_OBH + off));
                    LDMX4(bl4, smem_u32(s + G_OBL + off));
                    #pragma unroll
                    for (int mi = 0; mi < 2; mi++) {
                        MMA16816(d[mi][2 * p],     ah[mi], bh4);
                        MMA16816(d[mi][2 * p],     al[mi], bh4);
                        MMA16816(d[mi][2 * p],     ah[mi], bl4);
                        MMA16816(d[mi][2 * p + 1], ah[mi], bh4 + 2);
                        MMA16816(d[mi][2 * p + 1], al[mi], bh4 + 2);
                        MMA16816(d[mi][2 * p + 1], ah[mi], bl4 + 2);
                    }
                }
            }
            __syncthreads();
            if (ich + 2 < nch) issue(ich + 2, ich & 1);
        }

        // epilogue
        if (score_mode == 3 && bn == 2) {
            #pragma unroll
            for (int mi = 0; mi < 2; mi++) {
                int row = bm * 128 + wm * 32 + mi * 16 + (lane >> 2);
                #pragma unroll
                for (int ni = 0; ni < 8; ni++) {
                    int col = wn * 64 + ni * 8 + (lane & 3) * 2;
                    float b0 = bias2[col], b1 = bias2[col + 1];
                    *(float2*)(C2 + (size_t)row * 128 + col) =
                        make_float2(d[mi][ni][0] + b0, d[mi][ni][1] + b1);
                    *(float2*)(C2 + (size_t)(row + 8) * 128 + col) =
                        make_float2(d[mi][ni][2] + b0, d[mi][ni][3] + b1);
                }
            }
        } else {
            int outN = (score_mode == 3) ? 256 : N;
            #pragma unroll
            for (int mi = 0; mi < 2; mi++) {
                int row = bm * 128 + wm * 32 + mi * 16 + (lane >> 2);
                #pragma unroll
                for (int ni = 0; ni < 8; ni++) {
                    int col = bn * 128 + wn * 64 + ni * 8 + (lane & 3) * 2;
                    if (C) {
                        float b0 = bias ? bias[col] : 0.f;
                        float b1 = bias ? bias[col + 1] : 0.f;
                        *(float2*)(C + (size_t)row * outN + col) =
                            make_float2(d[mi][ni][0] + b0, d[mi][ni][1] + b1);
                        *(float2*)(C + (size_t)(row + 8) * outN + col) =
                            make_float2(d[mi][ni][2] + b0, d[mi][ni][3] + b1);
                    } else {
                        uint32_t hh, ll;
                        split2(d[mi][ni][0], d[mi][ni][1], hh, ll);
                        *(uint32_t*)(Chi + (size_t)row * outN + col) = hh;
                        *(uint32_t*)(Clo + (size_t)row * outN + col) = ll;
                        split2(d[mi][ni][2], d[mi][ni][3], hh, ll);
                        *(uint32_t*)(Chi + (size_t)(row + 8) * outN + col) = hh;
                        *(uint32_t*)(Clo + (size_t)(row + 8) * outN + col) = ll;
                    }
                }
            }
        }
        if (score_mode == 1 || (score_mode == 3 && bn < 2)) {
            int hd = bn * 2 + wn;
            float sv[4] = {0.f, 0.f, 0.f, 0.f}, dv[4] = {0.f, 0.f, 0.f, 0.f};
            #pragma unroll
            for (int mi = 0; mi < 2; mi++)
                #pragma unroll
                for (int ni = 0; ni < 8; ni++)
                    #pragma unroll
                    for (int j = 0; j < 2; j++) {
                        int cl = ni * 8 + (lane & 3) * 2 + j;
                        float a = asv[hd * 64 + cl], b = adv[hd * 64 + cl];
                        sv[mi * 2]     += d[mi][ni][j]     * a;
                        dv[mi * 2]     += d[mi][ni][j]     * b;
                        sv[mi * 2 + 1] += d[mi][ni][2 + j] * a;
                        dv[mi * 2 + 1] += d[mi][ni][2 + j] * b;
                    }
            #pragma unroll
            for (int r = 0; r < 4; r++) {
                sv[r] += __shfl_xor_sync(0xffffffffu, sv[r], 1);
                sv[r] += __shfl_xor_sync(0xffffffffu, sv[r], 2);
                dv[r] += __shfl_xor_sync(0xffffffffu, dv[r], 1);
                dv[r] += __shfl_xor_sync(0xffffffffu, dv[r], 2);
            }
            if ((lane & 3) == 0) {
                #pragma unroll
                for (int r = 0; r < 4; r++) {
                    int row = bm * 128 + wm * 32 + (r >> 1) * 16 + (lane >> 2) + (r & 1) * 8;
                    esv[(size_t)row * 4 + hd]     = sv[r];
                    edv_out[(size_t)row * 4 + hd] = dv[r];
                }
            }
        } else if (score_mode == 2) {
            float* reds = (float*)smem;
            float* redd = reds + 256;
            float sv[4] = {0.f, 0.f, 0.f, 0.f}, dv[4] = {0.f, 0.f, 0.f, 0.f};
            #pragma unroll
            for (int mi = 0; mi < 2; mi++)
                #pragma unroll
                for (int ni = 0; ni < 8; ni++)
                    #pragma unroll
                    for (int j = 0; j < 2; j++) {
                        int cl = wn * 64 + ni * 8 + (lane & 3) * 2 + j;
                        float a = asv[cl], b = adv[cl];
                        sv[mi * 2]     += d[mi][ni][j]     * a;
                        dv[mi * 2]     += d[mi][ni][j]     * b;
                        sv[mi * 2 + 1] += d[mi][ni][2 + j] * a;
                        dv[mi * 2 + 1] += d[mi][ni][2 + j] * b;
                    }
            #pragma unroll
            for (int r = 0; r < 4; r++) {
                sv[r] += __shfl_xor_sync(0xffffffffu, sv[r], 1);
                sv[r] += __shfl_xor_sync(0xffffffffu, sv[r], 2);
                dv[r] += __shfl_xor_sync(0xffffffffu, dv[r], 1);
                dv[r] += __shfl_xor_sync(0xffffffffu, dv[r], 2);
            }
            __syncthreads();
            if ((lane & 3) == 0) {
                #pragma unroll
                for (int r = 0; r < 4; r++) {
                    int row = wm * 32 + (r >> 1) * 16 + (lane >> 2) + (r & 1) * 8;
                    reds[row * 2 + wn] = sv[r];
                    redd[row * 2 + wn] = dv[r];
                }
            }
            __syncthreads();
            if (tid < 128) {
                esv[(size_t)(bm * 128 + tid)]     = reds[tid * 2] + reds[tid * 2 + 1];
                edv_out[(size_t)(bm * 128 + tid)] = redd[tid * 2] + redd[tid * 2 + 1];
            }
            __syncthreads();
        }
    }
}

// ================= QKV fused GEMM (persistent) =================
__global__ __launch_bounds__(256, 2) void mma_gemm_qkv(
    const __nv_bfloat16* __restrict__ Ah, const __nv_bfloat16* __restrict__ Al,
    const __nv_bfloat16* __restrict__ Bh, const __nv_bfloat16* __restrict__ Bl,
    __nv_bfloat16* __restrict__ QH, __nv_bfloat16* __restrict__ QL,
    __nv_bfloat16* __restrict__ KH, __nv_bfloat16* __restrict__ KL,
    __nv_bfloat16* __restrict__ VH, __nv_bfloat16* __restrict__ VL)
{
    constexpr int K = 128;
    constexpr int nch = K >> 5;
    extern __shared__ __nv_bfloat16 smem[];
    int tid = threadIdx.x, lane = tid & 31, warp = tid >> 5;
    int wm = warp & 3, wn = warp >> 2;
    int row_c = tid >> 2, seg_c = (tid & 3) * 8;
    constexpr int ntiles = 3 * 512;

    for (int tile = blockIdx.x; tile < ntiles; tile += gridDim.x) {
        int bm = tile / 3, bn = tile - bm * 3;
        const __nv_bfloat16* gAh = Ah + (size_t)bm * 128 * K;
        const __nv_bfloat16* gAl = Al + (size_t)bm * 128 * K;
        const __nv_bfloat16* gBh = Bh + (size_t)bn * 128 * K;
        const __nv_bfloat16* gBl = Bl + (size_t)bn * 128 * K;

        auto issue = [&](int ich, int st) {
            int k0 = ich << 5;
            __nv_bfloat16* s = smem + st * G_STAGE;
            #pragma unroll
            for (int r = 0; r < 2; r++) {
                int row = row_c + r * 64;
                size_t go = (size_t)row * K + k0 + seg_c;
                int so = row * LDS_ + seg_c;
                CP16(smem_u32(s + so), gAh + go);
                CP16(smem_u32(s + G_OAL + so), gAl + go);
                CP16(smem_u32(s + G_OBH + so), gBh + go);
                CP16(smem_u32(s + G_OBL + so), gBl + go);
            }
            CP_COMMIT();
        };

        float d[2][8][4];
        #pragma unroll
        for (int mi = 0; mi < 2; mi++)
            #pragma unroll
            for (int ni = 0; ni < 8; ni++)
                #pragma unroll
                for (int j = 0; j < 4; j++) d[mi][ni][j] = 0.f;

        issue(0, 0);
        issue(1, 1);
        for (int ich = 0; ich < nch; ich++) {
            if (ich + 1 < nch) CP_WAIT1(); else CP_WAIT0();
            __syncthreads();
            const __nv_bfloat16* s = smem + (ich & 1) * G_STAGE;
            #pragma unroll
            for (int ks = 0; ks < 2; ks++) {
                uint32_t ah[2][4], al[2][4];
                #pragma unroll
                for (int mi = 0; mi < 2; mi++) {
                    int row = wm * 32 + mi * 16 + (lane & 15);
                    int col = ks * 16 + (lane >> 4) * 8;
                    LDMX4(ah[mi], smem_u32(s + row * LDS_ + col));
                    LDMX4(al[mi], smem_u32(s + G_OAL + row * LDS_ + col));
                }
                int brow = wn * 64 + ((lane >> 4) & 1) * 8 + (lane & 7);
                int bcol = ks * 16 + ((lane >> 3) & 1) * 8;
                #pragma unroll
                for (int p = 0; p < 4; p++) {
                    uint32_t bh4[4], bl4[4];
                    int off = (brow + p * 16) * LDS_ + bcol;
                    LDMX4(bh4, smem_u32(s + G_OBH + off));
                    LDMX4(bl4, smem_u32(s + G_OBL + off));
                    #pragma unroll
                    for (int mi = 0; mi < 2; mi++) {
                        MMA16816(d[mi][2 * p],     ah[mi], bh4);
                        MMA16816(d[mi][2 * p],     al[mi], bh4);
                        MMA16816(d[mi][2 * p],     ah[mi], bl4);
                        MMA16816(d[mi][2 * p + 1], ah[mi], bh4 + 2);
                        MMA16816(d[mi][2 * p + 1], al[mi], bh4 + 2);
                        MMA16816(d[mi][2 * p + 1], ah[mi], bl4 + 2);
                    }
                }
            }
            __syncthreads();
            if (ich + 2 < nch) issue(ich + 2, ich & 1);
        }
        __nv_bfloat16 *Oh, *Ol;
        if (bn == 0)      { Oh = QH; Ol = QL; }
        else if (bn == 1) { Oh = KH; Ol = KL; }
        else              { Oh = VH; Ol = VL; }
        #pragma unroll
        for (int mi = 0; mi < 2; mi++) {
            int row = bm * 128 + wm * 32 + mi * 16 + (lane >> 2);
            #pragma unroll
            for (int ni = 0; ni < 8; ni++) {
                int col = wn * 64 + ni * 8 + (lane & 3) * 2;
                uint32_t hh, ll;
                split2(d[mi][ni][0], d[mi][ni][1], hh, ll);
                *(uint32_t*)(Oh + (size_t)row * 128 + col) = hh;
                *(uint32_t*)(Ol + (size_t)row * 128 + col) = ll;
                split2(d[mi][ni][2], d[mi][ni][3], hh, ll);
                *(uint32_t*)(Oh + (size_t)(row + 8) * 128 + col) = hh;
                *(uint32_t*)(Ol + (size_t)(row + 8) * 128 + col) = ll;
            }
        }
    }
}

// ================= GAT aggregation — single pass, float4 vectorized ==========
template <int D, int H>
__global__ __launch_bounds__(256) void k_gat_agg(
    const float* __restrict__ hfeat, const float* __restrict__ es,
    const float* __restrict__ ed, const float* __restrict__ bias,
    const float* __restrict__ gamma, const float* __restrict__ beta,
    const float* __restrict__ resid,
    __nv_bfloat16* __restrict__ outH, __nv_bfloat16* __restrict__ outL)
{
    constexpr int C = D / H;
    constexpr int NV = D / 128;
    int warp = (blockIdx.x * blockDim.x + threadIdx.x) >> 5;
    int lane = threadIdx.x & 31;
    if (warp >= NN) return;
    int i = warp;
    int beg = g_rowptr[i], end = g_rowptr[i + 1];

    float edv[H], z[H];
    #pragma unroll
    for (int h = 0; h < H; h++) {
        edv[h] = ed[(size_t)i * H + h];
        z[h] = 0.f;
    }
    float4 acc[NV];
    #pragma unroll
    for (int j = 0; j < NV; j++) acc[j] = make_float4(0.f, 0.f, 0.f, 0.f);

    for (int e = beg; e < end; e++) {
        int s = g_col[e];
        float al[H];
        if (H == 4) {
            float4 ev = ((const float4*)es)[s];
            float vv[4] = {ev.x, ev.y, ev.z, ev.w};
            #pragma unroll
            for (int h = 0; h < 4; h++) {
                float v = vv[h] + edv[h];
                v = v > 0.f ? v : 0.2f * v;
                al[h] = __expf(v);
                z[h] += al[h];
            }
        } else {
            float v = es[s] + edv[0];
            v = v > 0.f ? v : 0.2f * v;
            al[0] = __expf(v);
            z[0] += al[0];
        }
        const float4* hs = (const float4*)(hfeat + (size_t)s * D);
        #pragma unroll
        for (int j = 0; j < NV; j++) {
            float4 hv = hs[lane + 32 * j];
            float a = (H == 1) ? al[0] : al[((lane + 32 * j) * 4) / C];
            acc[j].x += a * hv.x; acc[j].y += a * hv.y;
            acc[j].z += a * hv.z; acc[j].w += a * hv.w;
        }
    }
    #pragma unroll
    for (int h = 0; h < H; h++) z[h] = 1.f / (z[h] + 1e-16f);

    float4 x[NV];
    #pragma unroll
    for (int j = 0; j < NV; j++) {
        int g4 = lane + 32 * j;
        float zz = (H == 1) ? z[0] : z[(g4 * 4) / C];
        float4 b4 = ((const float4*)bias)[g4];
        x[j].x = acc[j].x * zz + b4.x;
        x[j].y = acc[j].y * zz + b4.y;
        x[j].z = acc[j].z * zz + b4.z;
        x[j].w = acc[j].w * zz + b4.w;
        if (resid) {
            float4 r4 = ((const float4*)(resid + (size_t)i * D))[g4];
            x[j].x += r4.x; x[j].y += r4.y; x[j].z += r4.z; x[j].w += r4.w;
        }
    }
    if (gamma) {
        #pragma unroll
        for (int j = 0; j < NV; j++) {
            x[j].x = x[j].x > 0.f ? x[j].x : (__expf(x[j].x) - 1.f);
            x[j].y = x[j].y > 0.f ? x[j].y : (__expf(x[j].y) - 1.f);
            x[j].z = x[j].z > 0.f ? x[j].z : (__expf(x[j].z) - 1.f);
            x[j].w = x[j].w > 0.f ? x[j].w : (__expf(x[j].w) - 1.f);
        }
        float s = 0.f;
        #pragma unroll
        for (int j = 0; j < NV; j++) s += x[j].x + x[j].y + x[j].z + x[j].w;
        #pragma unroll
        for (int o = 16; o; o >>= 1) s += __shfl_xor_sync(0xffffffffu, s, o);
        float mu = s / (float)D;
        float vs = 0.f;
        #pragma unroll
        for (int j = 0; j < NV; j++) {
            float a = x[j].x - mu, b = x[j].y - mu, c = x[j].z - mu, dd = x[j].w - mu;
            vs += a * a + b * b + c * c + dd * dd;
        }
        #pragma unroll
        for (int o = 16; o; o >>= 1) vs += __shfl_xor_sync(0xffffffffu, vs, o);
        float inv = rsqrtf(vs / (float)D + 1e-5f);
        #pragma unroll
        for (int j = 0; j < NV; j++) {
            int g4 = lane + 32 * j;
            float4 g = ((const float4*)gamma)[g4];
            float4 be = ((const float4*)beta)[g4];
            x[j].x = (x[j].x - mu) * inv * g.x + be.x;
            x[j].y = (x[j].y - mu) * inv * g.y + be.y;
            x[j].z = (x[j].z - mu) * inv * g.z + be.z;
            x[j].w = (x[j].w - mu) * inv * g.w + be.w;
        }
    }
    #pragma unroll
    for (int j = 0; j < NV; j++) {
        int g4 = lane + 32 * j;
        uint32_t h01, l01, h23, l23;
        split2(x[j].x, x[j].y, h01, l01);
        split2(x[j].z, x[j].w, h23, l23);
        *(uint2*)(outH + (size_t)i * D + g4 * 4) = make_uint2(h01, h23);
        *(uint2*)(outL + (size_t)i * D + g4 * 4) = make_uint2(l01, l23);
    }
}

// ============ fused flash attention, cp.async K/V pipeline (non-persistent) ==
constexpr int FL_QH = 0;
constexpr int FL_QL = 128 * LDS_;
constexpr int FL_ST0 = 2 * 128 * LDS_;
constexpr int FL_KH = 0;
constexpr int FL_KL = 128 * LDS_;
constexpr int FL_VH = 2 * 128 * LDS_;
constexpr int FL_VL = 3 * 128 * LDS_;
constexpr int FL_STAGE = 4 * 128 * LDS_;
constexpr int FLASH_SMEM = (FL_ST0 + 2 * FL_STAGE) * 2;   // 102400 bytes

__global__ __launch_bounds__(256, 2) void k_flash(
    const __nv_bfloat16* __restrict__ QH, const __nv_bfloat16* __restrict__ QL,
    const __nv_bfloat16* __restrict__ KH, const __nv_bfloat16* __restrict__ KL,
    const __nv_bfloat16* __restrict__ VH, const __nv_bfloat16* __restrict__ VL,
    __nv_bfloat16* __restrict__ OHo, __nv_bfloat16* __restrict__ OLo)
{
    extern __shared__ __nv_bfloat16 sm[];
    int gh = blockIdx.y, g = gh >> 2, h = gh & 3;
    int qt = blockIdx.x;
    int tid = threadIdx.x, lane = tid & 31, warp = tid >> 5;

    int row_c = tid >> 2, seg_c = (tid & 3) * 8;

    auto issue = [&](int kt, int st) {
        __nv_bfloat16* s = sm + FL_ST0 + st * FL_STAGE;
        #pragma unroll
        for (int r = 0; r < 2; r++) {
            int row = row_c + r * 64;
            size_t go = ((size_t)g * GS + kt * 128 + row) * 128 + h * 32 + seg_c;
            int so = row * LDS_ + seg_c;
            CP16(smem_u32(s + FL_KH + so), KH + go);
            CP16(smem_u32(s + FL_KL + so), KL + go);
            CP16(smem_u32(s + FL_VH + so), VH + go);
            CP16(smem_u32(s + FL_VL + so), VL + go);
        }
        CP_COMMIT();
    };

    {
        #pragma unroll
        for (int r = 0; r < 2; r++) {
            int row = row_c + r * 64;
            size_t go = ((size_t)g * GS + qt * 128 + row) * 128 + h * 32 + seg_c;
            int so = row * LDS_ + seg_c;
            CP16(smem_u32(sm + FL_QH + so), QH + go);
            CP16(smem_u32(sm + FL_QL + so), QL + go);
        }
        __nv_bfloat16* s = sm + FL_ST0;
        #pragma unroll
        for (int r = 0; r < 2; r++) {
            int row = row_c + r * 64;
            size_t go = ((size_t)g * GS + row) * 128 + h * 32 + seg_c;
            int so = row * LDS_ + seg_c;
            CP16(smem_u32(s + FL_KH + so), KH + go);
            CP16(smem_u32(s + FL_KL + so), KL + go);
            CP16(smem_u32(s + FL_VH + so), VH + go);
            CP16(smem_u32(s + FL_VL + so), VL + go);
        }
        CP_COMMIT();
    }
    issue(1, 1);

    uint32_t qh_[2][4], ql_[2][4];
    float m0 = -1e30f, m1 = -1e30f, l0 = 0.f, l1 = 0.f;
    float O[4][4];
    #pragma unroll
    for (int n = 0; n < 4; n++)
        #pragma unroll
        for (int j = 0; j < 4; j++) O[n][j] = 0.f;

    const float scale = 0.088388347648318447f;

    for (int kt = 0; kt < 4; kt++) {
        if (kt < 3) CP_WAIT1(); else CP_WAIT0();
        __syncthreads();
        const __nv_bfloat16* s = sm + FL_ST0 + (kt & 1) * FL_STAGE;

        if (kt == 0) {
            #pragma unroll
            for (int kf = 0; kf < 2; kf++) {
                int row = warp * 16 + (lane & 15);
                int col = kf * 16 + (lane >> 4) * 8;
                LDMX4(qh_[kf], smem_u32(sm + FL_QH + row * LDS_ + col));
                LDMX4(ql_[kf], smem_u32(sm + FL_QL + row * LDS_ + col));
            }
        }

        float S[16][4];
        #pragma unroll
        for (int j = 0; j < 16; j++)
            #pragma unroll
            for (int r = 0; r < 4; r++) S[j][r] = 0.f;
        {
            int brow = ((lane >> 4) & 1) * 8 + (lane & 7);
            #pragma unroll
            for (int jp = 0; jp < 8; jp++) {
                #pragma unroll
                for (int kf = 0; kf < 2; kf++) {
                    uint32_t bh4[4], bl4[4];
                    int off = (jp * 16 + brow) * LDS_ + kf * 16 + ((lane >> 3) & 1) * 8;
                    LDMX4(bh4, smem_u32(s + FL_KH + off));
                    LDMX4(bl4, smem_u32(s + FL_KL + off));
                    MMA16816(S[2 * jp],     qh_[kf], bh4);
                    MMA16816(S[2 * jp],     ql_[kf], bh4);
                    MMA16816(S[2 * jp],     qh_[kf], bl4);
                    MMA16816(S[2 * jp + 1], qh_[kf], bh4 + 2);
                    MMA16816(S[2 * jp + 1], ql_[kf], bh4 + 2);
                    MMA16816(S[2 * jp + 1], qh_[kf], bl4 + 2);
                }
            }
        }
        float mx0 = -1e30f, mx1 = -1e30f;
        #pragma unroll
        for (int j = 0; j < 16; j++) {
            S[j][0] *= scale; S[j][1] *= scale; S[j][2] *= scale; S[j][3] *= scale;
            mx0 = fmaxf(mx0, fmaxf(S[j][0], S[j][1]));
            mx1 = fmaxf(mx1, fmaxf(S[j][2], S[j][3]));
        }
        #pragma unroll
        for (int o = 1; o < 4; o <<= 1) {
            mx0 = fmaxf(mx0, __shfl_xor_sync(0xffffffffu, mx0, o));
            mx1 = fmaxf(mx1, __shfl_xor_sync(0xffffffffu, mx1, o));
        }
        float nm0 = fmaxf(m0, mx0), nm1 = fmaxf(m1, mx1);
        float a0 = __expf(m0 - nm0), a1 = __expf(m1 - nm1);
        float rs0 = 0.f, rs1 = 0.f;
        #pragma unroll
        for (int j = 0; j < 16; j++) {
            S[j][0] = __expf(S[j][0] - nm0); S[j][1] = __expf(S[j][1] - nm0);
            S[j][2] = __expf(S[j][2] - nm1); S[j][3] = __expf(S[j][3] - nm1);
            rs0 += S[j][0] + S[j][1];
            rs1 += S[j][2] + S[j][3];
        }
        #pragma unroll
        for (int o = 1; o < 4; o <<= 1) {
            rs0 += __shfl_xor_sync(0xffffffffu, rs0, o);
            rs1 += __shfl_xor_sync(0xffffffffu, rs1, o);
        }
        l0 = l0 * a0 + rs0;
        l1 = l1 * a1 + rs1;
        #pragma unroll
        for (int n = 0; n < 4; n++) {
            O[n][0] *= a0; O[n][1] *= a0; O[n][2] *= a1; O[n][3] *= a1;
        }
        m0 = nm0; m1 = nm1;
        #pragma unroll
        for (int jp = 0; jp < 8; jp++) {
            uint32_t aph[4], apl[4];
            split2(S[2 * jp][0],     S[2 * jp][1],     aph[0], apl[0]);
            split2(S[2 * jp][2],     S[2 * jp][3],     aph[1], apl[1]);
            split2(S[2 * jp + 1][0], S[2 * jp + 1][1], aph[2], apl[2]);
            split2(S[2 * jp + 1][2], S[2 * jp + 1][3], aph[3], apl[3]);
            int vrow = jp * 16 + ((lane >> 3) & 1) * 8 + (lane & 7);
            #pragma unroll
            for (int np = 0; np < 2; np++) {
                uint32_t bh4[4], bl4[4];
                int off = vrow * LDS_ + (2 * np + ((lane >> 4) & 1)) * 8;
                LDMX4T(bh4, smem_u32(s + FL_VH + off));
                LDMX4T(bl4, smem_u32(s + FL_VL + off));
                MMA16816(O[2 * np],     aph, bh4);
                MMA16816(O[2 * np],     apl, bh4);
                MMA16816(O[2 * np],     aph, bl4);
                MMA16816(O[2 * np + 1], aph, bh4 + 2);
                MMA16816(O[2 * np + 1], apl, bh4 + 2);
                MMA16816(O[2 * np + 1], aph, bl4 + 2);
            }
        }
        __syncthreads();
        if (kt + 2 < 4) issue(kt + 2, kt & 1);
    }
    float il0 = 1.f / l0, il1 = 1.f / l1;
    int node = g * GS + qt * 128 + warp * 16 + (lane >> 2);
    #pragma unroll
    for (int n = 0; n < 4; n++) {
        int col = h * 32 + n * 8 + (lane & 3) * 2;
        uint32_t hh, ll;
        split2(O[n][0] * il0, O[n][1] * il0, hh, ll);
        *(uint32_t*)(OHo + (size_t)node * 128 + col) = hh;
        *(uint32_t*)(OLo + (size_t)node * 128 + col) = ll;
        split2(O[n][2] * il1, O[n][3] * il1, hh, ll);
        *(uint32_t*)(OHo + (size_t)(node + 8) * 128 + col) = hh;
        *(uint32_t*)(OLo + (size_t)(node + 8) * 128 + col) = ll;
    }
}

// ================= host orchestration =================
extern "C" void kernel_launch(void* const* d_in, const int* in_sizes, int n_in,
                              void* d_out, int out_size)
{
    const float* x   = (const float*)d_in[0];
    const int*   ei  = (const int*)  d_in[1];
    const float* W1  = (const float*)d_in[3];
    const float* a1s = (const float*)d_in[4];
    const float* a1d = (const float*)d_in[5];
    const float* b1  = (const float*)d_in[6];
    const float* W2  = (const float*)d_in[7];
    const float* a2s = (const float*)d_in[8];
    const float* a2d = (const float*)d_in[9];
    const float* b2  = (const float*)d_in[10];
    const float* W3  = (const float*)d_in[11];
    const float* a3s = (const float*)d_in[12];
    const float* a3d = (const float*)d_in[13];
    const float* b3  = (const float*)d_in[14];
    const float* g1  = (const float*)d_in[15];
    const float* be1 = (const float*)d_in[16];
    const float* g2  = (const float*)d_in[17];
    const float* be2 = (const float*)d_in[18];
    const float* Wr  = (const float*)d_in[19];
    const float* br  = (const float*)d_in[20];
    const float* Wq  = (const float*)d_in[21];
    const float* Wk  = (const float*)d_in[22];
    const float* Wv  = (const float*)d_in[23];
    const float* Wo  = (const float*)d_in[24];
    const float* bo  = (const float*)d_in[25];
    float* out = (float*)d_out;

    float* sb = nullptr;
    cudaGetSymbolAddress((void**)&sb, g_scratch);
    __nv_bfloat16* bb = nullptr;
    cudaGetSymbolAddress((void**)&bb, g_bf);
    cudaFuncSetAttribute(k_flash, cudaFuncAttributeMaxDynamicSharedMemorySize, FLASH_SMEM);
    cudaFuncSetAttribute(mma_gemm, cudaFuncAttributeMaxDynamicSharedMemorySize, GEMM_SMEM);
    cudaFuncSetAttribute(mma_gemm_qkv, cudaFuncAttributeMaxDynamicSharedMemorySize, GEMM_SMEM);

    float* p_h  = sb + OFF_H;
    float* p_h3 = sb + OFF_H3;
    float* p_r  = sb + OFF_R;
    float* p_es = sb + OFF_ES;
    float* p_ed = sb + OFF_ED;

    // conversions + g_cnt zeroing (one launch), then CSR (vectorized)
    k_cvt_all<<<(CVT_TOTAL + 255) / 256, 256>>>(W1, Wr, W2, W3, Wq, Wk, Wv, Wo, x);
    k_count<<<(NE / 4 + 255) / 256, 256>>>(ei);
    k_scan1<<<256, 256>>>();
    k_scan3<<<256, 256>>>();
    k_fill<<<(FILL_THREADS + 255) / 256, 256>>>(ei);

    // layer 1 combo: h (+H=4 scores) AND residual p_r in one GEMM (N=384)
    mma_gemm<<<PERS, 256, GEMM_SMEM>>>(bb + B_XH, bb + B_XL, bb + B_W1RH, bb + B_W1RL,
                                    nullptr, p_h, nullptr, nullptr, p_r, br,
                                    a1s, a1d, p_es, p_ed, 3, NN, 384, 64);
    k_gat_agg<256, 4><<<NN / 8, 256>>>(p_h, p_es, p_ed, b1, g1, be1, nullptr,
                                       bb + B_TH, bb + B_TL);
    // layer 2 (fused H=4 scores)
    mma_gemm<<<PERS, 256, GEMM_SMEM>>>(bb + B_TH, bb + B_TL, bb + B_W2H, bb + B_W2L,
                                    nullptr, p_h, nullptr, nullptr, nullptr, nullptr,
                                    a2s, a2d, p_es, p_ed, 1, NN, 256, 256);
    k_gat_agg<256, 4><<<NN / 8, 256>>>(p_h, p_es, p_ed, b2, g2, be2, nullptr,
                                       bb + B_TH, bb + B_TL);
    // layer 3 (fused H=1 scores)
    mma_gemm<<<PERS, 256, GEMM_SMEM>>>(bb + B_TH, bb + B_TL, bb + B_W3H, bb + B_W3L,
                                    nullptr, p_h3, nullptr, nullptr, nullptr, nullptr,
                                    a3s, a3d, p_es, p_ed, 2, NN, 128, 256);
    k_gat_agg<128, 1><<<NN / 8, 256>>>(p_h3, p_es, p_ed, b3, nullptr, nullptr, p_r,
                                       bb + B_HRH, bb + B_HRL);
    // fused QKV projection
    mma_gemm_qkv<<<PERS, 256, GEMM_SMEM>>>(bb + B_HRH, bb + B_HRL,
                                        bb + B_WQKVH, bb + B_WQKVL,
                                        bb + B_QH, bb + B_QL,
                                        bb + B_KH, bb + B_KL,
                                        bb + B_VH, bb + B_VL);
    // fused attention (non-persistent — best measured config)
    k_flash<<<dim3(4, NG * 4), 256, FLASH_SMEM>>>(
        bb + B_QH, bb + B_QL, bb + B_KH, bb + B_KL,
        bb + B_VH, bb + B_VL, bb + B_AOH, bb + B_AOL);
    // output projection
    mma_gemm<<<PERS, 256, GEMM_SMEM>>>(bb + B_AOH, bb + B_AOL, bb + B_WOH, bb + B_WOL,
                                    bo, out, nullptr, nullptr, nullptr, nullptr,
                                    nullptr, nullptr, nullptr, nullptr, 0, NN, 128, 128);
}